// round 6
// baseline (speedup 1.0000x reference)
#include <cuda_runtime.h>
#include <cuda_bf16.h>
#include <stdint.h>
#include <math.h>

#define BATCH 2
#define SEQ   2048
#define DIM   1024
#define ROWS  (BATCH*SEQ)   // 4096
#define NH    16
#define DH    64

// Scratch (allocation-free rule: __device__ globals)
__device__ __nv_bfloat16 g_ah[ROWS*DIM];   // x_norm split hi, later attn-out hi
__device__ __nv_bfloat16 g_al[ROWS*DIM];   // x_norm split lo, later attn-out lo
__device__ __nv_bfloat16 g_th[DIM*DIM];    // W^T split hi  [N][K]
__device__ __nv_bfloat16 g_tl[DIM*DIM];    // W^T split lo  [N][K]
__device__ __nv_bfloat16 g_qh[ROWS*DIM];   // Q hi (roped) [bh][s][d]
__device__ __nv_bfloat16 g_ql[ROWS*DIM];   // Q lo
__device__ __nv_bfloat16 g_kh[ROWS*DIM];   // K hi (roped) [bh][s][d]
__device__ __nv_bfloat16 g_kl[ROWS*DIM];   // K lo
__device__ __nv_bfloat16 g_vh[ROWS*DIM];   // V hi [bh][s][d]
__device__ __nv_bfloat16 g_vl[ROWS*DIM];   // V lo

// ===========================================================================
// Portable (compute_103-safe) PTX helpers
// ===========================================================================
__device__ __forceinline__ uint32_t smem_u32(const void* p) {
    uint32_t a;
    asm("{ .reg .u64 t; cvta.to.shared.u64 t, %1; cvt.u32.u64 %0, t; }"
        : "=r"(a) : "l"(p));
    return a;
}
__device__ __forceinline__ void cp_async16(uint32_t saddr, const void* gaddr) {
    asm volatile("cp.async.cg.shared.global [%0], [%1], 16;"
                 :: "r"(saddr), "l"(gaddr));
}
__device__ __forceinline__ void cp_commit() {
    asm volatile("cp.async.commit_group;" ::: "memory");
}
__device__ __forceinline__ void ldsm4(uint32_t* r, uint32_t addr) {
    asm volatile("ldmatrix.sync.aligned.m8n8.x4.shared.b16 {%0,%1,%2,%3}, [%4];"
                 : "=r"(r[0]), "=r"(r[1]), "=r"(r[2]), "=r"(r[3]) : "r"(addr));
}
__device__ __forceinline__ void ldsm4t(uint32_t* r, uint32_t addr) {
    asm volatile("ldmatrix.sync.aligned.m8n8.x4.trans.shared.b16 {%0,%1,%2,%3}, [%4];"
                 : "=r"(r[0]), "=r"(r[1]), "=r"(r[2]), "=r"(r[3]) : "r"(addr));
}
__device__ __forceinline__ void mma16816(float* c, const uint32_t* a,
                                         uint32_t b0, uint32_t b1) {
    asm volatile(
        "mma.sync.aligned.m16n8k16.row.col.f32.bf16.bf16.f32 "
        "{%0,%1,%2,%3}, {%4,%5,%6,%7}, {%8,%9}, {%0,%1,%2,%3};"
        : "+f"(c[0]), "+f"(c[1]), "+f"(c[2]), "+f"(c[3])
        : "r"(a[0]), "r"(a[1]), "r"(a[2]), "r"(a[3]), "r"(b0), "r"(b1));
}
__device__ __forceinline__ uint32_t pack2h(__nv_bfloat16 a, __nv_bfloat16 b) {
    __nv_bfloat162 t = __halves2bfloat162(a, b);
    return *reinterpret_cast<uint32_t*>(&t);
}
__device__ __forceinline__ uint32_t pack2f(float a, float b) {
    __nv_bfloat162 t = __floats2bfloat162_rn(a, b);
    return *reinterpret_cast<uint32_t*>(&t);
}
// split helper: hi = bf16(v), lo = bf16(v - hi)
__device__ __forceinline__ void split2(float a, float b, uint32_t& hi, uint32_t& lo) {
    __nv_bfloat16 ha = __float2bfloat16(a), hb = __float2bfloat16(b);
    hi = pack2h(ha, hb);
    lo = pack2f(a - __bfloat162float(ha), b - __bfloat162float(hb));
}

// ===========================================================================
// RMSNorm fused with bf16 split: x -> (ah, al)
// ===========================================================================
__global__ __launch_bounds__(256) void rmsnorm_split_kernel(
    const float* __restrict__ x, const float* __restrict__ sc,
    __nv_bfloat16* __restrict__ hi, __nv_bfloat16* __restrict__ lo)
{
    int row = blockIdx.x;
    const float* xr = x + (size_t)row * DIM;
    float ss = 0.f;
    #pragma unroll
    for (int i = threadIdx.x; i < DIM; i += 256) {
        float v = xr[i];
        ss = fmaf(v, v, ss);
    }
    __shared__ float red[256];
    red[threadIdx.x] = ss;
    __syncthreads();
    #pragma unroll
    for (int s = 128; s > 0; s >>= 1) {
        if (threadIdx.x < s) red[threadIdx.x] += red[threadIdx.x + s];
        __syncthreads();
    }
    float r = rsqrtf(red[0] * (1.0f / DIM) + 1e-6f);
    #pragma unroll
    for (int i = threadIdx.x; i < DIM; i += 256) {
        float y = xr[i] * r * sc[i];
        __nv_bfloat16 h = __float2bfloat16(y);
        hi[(size_t)row * DIM + i] = h;
        lo[(size_t)row * DIM + i] = __float2bfloat16(y - __bfloat162float(h));
    }
}

// ===========================================================================
// Transpose + split: W [K=1024][N=1024] fp32 -> T_hi/T_lo [N][K] bf16
// ===========================================================================
__global__ __launch_bounds__(256) void wsplit_kernel(
    const float* __restrict__ W,
    __nv_bfloat16* __restrict__ Th, __nv_bfloat16* __restrict__ Tl)
{
    __shared__ float tile[32][33];
    int k0 = blockIdx.y * 32, n0 = blockIdx.x * 32;
    int tx = threadIdx.x & 31, ty = threadIdx.x >> 5;   // 32 x 8
    #pragma unroll
    for (int i = 0; i < 32; i += 8)
        tile[ty + i][tx] = W[(size_t)(k0 + ty + i) * DIM + n0 + tx];
    __syncthreads();
    #pragma unroll
    for (int i = 0; i < 32; i += 8) {
        float v = tile[tx][ty + i];    // = W[k0+tx][n0+ty+i]
        __nv_bfloat16 h = __float2bfloat16(v);
        float r = v - __bfloat162float(h);
        size_t o = (size_t)(n0 + ty + i) * DIM + k0 + tx;
        Th[o] = h;
        Tl[o] = __float2bfloat16(r);
    }
}

// ===========================================================================
// bf16-split GEMM via mma.sync. Block tile 256x128, BK=32, 8 warps (4x2),
// warp tile 64x64. Epilogue MODE:
//   0 = RoPE + split -> (Dh, Dl) in [bh][s][d]    (Q, K)
//   1 = split        -> (Dh, Dl) in [bh][s][d]    (V)
//   2 = fp32         -> Cout [row][col]           (output projection)
// ===========================================================================
#define A_TILE_B 20480             // 256 rows x 80 bytes
#define B_TILE_B 10240             // 128 rows x 80 bytes
#define STG_B    (2*A_TILE_B + 2*B_TILE_B)   // 61440
#define GEMM_SMEM (2*STG_B)                   // 122880

template<int MODE>
__global__ __launch_bounds__(256) void mma_gemm_kernel(
    const __nv_bfloat16* __restrict__ Ah, const __nv_bfloat16* __restrict__ Al,
    const __nv_bfloat16* __restrict__ Bh, const __nv_bfloat16* __restrict__ Bl,
    __nv_bfloat16* __restrict__ Dh, __nv_bfloat16* __restrict__ Dl,
    float* __restrict__ Cout)
{
    extern __shared__ char smem[];
    uint32_t sb = smem_u32(smem);

    const int tid  = threadIdx.x;
    const int lane = tid & 31;
    const int wid  = tid >> 5;
    const int warp_m = wid & 3;
    const int warp_n = wid >> 2;
    const int bm = blockIdx.y * 256;
    const int bn = blockIdx.x * 128;

    float acc[4][8][4];
    #pragma unroll
    for (int i = 0; i < 4; i++)
        #pragma unroll
        for (int j = 0; j < 8; j++)
            #pragma unroll
            for (int q = 0; q < 4; q++) acc[i][j][q] = 0.f;

    auto load_stage = [&](int kt, int s) {
        const __nv_bfloat16* asrc[2] = {Ah, Al};
        #pragma unroll
        for (int t = 0; t < 2; t++) {
            #pragma unroll
            for (int i = 0; i < 4; i++) {
                int chunk = tid + i * 256;         // 0..1023
                int row = chunk >> 2, c = chunk & 3;
                cp_async16(sb + s * STG_B + t * A_TILE_B + row * 80 + c * 16,
                           asrc[t] + (size_t)(bm + row) * DIM + kt * 32 + c * 8);
            }
        }
        const __nv_bfloat16* bsrc[2] = {Bh, Bl};
        #pragma unroll
        for (int t = 0; t < 2; t++) {
            #pragma unroll
            for (int i = 0; i < 2; i++) {
                int chunk = tid + i * 256;         // 0..511
                int row = chunk >> 2, c = chunk & 3;
                cp_async16(sb + s * STG_B + 2 * A_TILE_B + t * B_TILE_B + row * 80 + c * 16,
                           bsrc[t] + (size_t)(bn + row) * DIM + kt * 32 + c * 8);
            }
        }
        cp_commit();
    };

    load_stage(0, 0);
    load_stage(1, 1);

    const int aRow = lane & 15;
    const int aK16 = (lane >> 4) * 16;
    const int bRow = (lane & 7) + ((lane >> 4) << 3);
    const int bK16 = ((lane >> 3) & 1) * 16;

    for (int kt = 0; kt < 32; kt++) {
        if (kt < 31) asm volatile("cp.async.wait_group 1;" ::: "memory");
        else         asm volatile("cp.async.wait_group 0;" ::: "memory");
        __syncthreads();

        uint32_t st  = sb + (kt & 1) * STG_B;
        uint32_t aHb = st + (warp_m * 64 + aRow) * 80 + aK16;
        uint32_t aLb = aHb + A_TILE_B;
        uint32_t bHb = st + 2 * A_TILE_B + (warp_n * 64 + bRow) * 80 + bK16;
        uint32_t bLb = bHb + B_TILE_B;

        #pragma unroll
        for (int ks = 0; ks < 2; ks++) {
            uint32_t koff = ks * 32;
            uint32_t fah[4][4], fal[4][4], fb[4][4];
            #pragma unroll
            for (int mt = 0; mt < 4; mt++) {
                ldsm4(fah[mt], aHb + mt * 1280 + koff);
                ldsm4(fal[mt], aLb + mt * 1280 + koff);
            }
            #pragma unroll
            for (int n2 = 0; n2 < 4; n2++)
                ldsm4(fb[n2], bHb + n2 * 1280 + koff);
            #pragma unroll
            for (int mt = 0; mt < 4; mt++)
                #pragma unroll
                for (int nt = 0; nt < 8; nt++)
                    mma16816(acc[mt][nt], fah[mt],
                             fb[nt >> 1][(nt & 1) * 2], fb[nt >> 1][(nt & 1) * 2 + 1]);
            #pragma unroll
            for (int mt = 0; mt < 4; mt++)
                #pragma unroll
                for (int nt = 0; nt < 8; nt++)
                    mma16816(acc[mt][nt], fal[mt],
                             fb[nt >> 1][(nt & 1) * 2], fb[nt >> 1][(nt & 1) * 2 + 1]);
            #pragma unroll
            for (int n2 = 0; n2 < 4; n2++)
                ldsm4(fb[n2], bLb + n2 * 1280 + koff);
            #pragma unroll
            for (int mt = 0; mt < 4; mt++)
                #pragma unroll
                for (int nt = 0; nt < 8; nt++)
                    mma16816(acc[mt][nt], fah[mt],
                             fb[nt >> 1][(nt & 1) * 2], fb[nt >> 1][(nt & 1) * 2 + 1]);
        }
        __syncthreads();
        if (kt + 2 < 32) load_stage(kt + 2, kt & 1);
    }

    const int g = lane >> 2, t2 = (lane & 3) * 2;

    if (MODE == 2) {
        #pragma unroll
        for (int mt = 0; mt < 4; mt++) {
            #pragma unroll
            for (int nt = 0; nt < 8; nt++) {
                int row = bm + warp_m * 64 + mt * 16 + g;
                int col = bn + warp_n * 64 + nt * 8 + t2;
                *(float2*)&Cout[(size_t)row * DIM + col] =
                    make_float2(acc[mt][nt][0], acc[mt][nt][1]);
                *(float2*)&Cout[(size_t)(row + 8) * DIM + col] =
                    make_float2(acc[mt][nt][2], acc[mt][nt][3]);
            }
        }
        return;
    }

    // head-local setup: warp's 64-col slab == one head
    const int h = (bn + warp_n * 64) >> 6;

    #pragma unroll
    for (int mt = 0; mt < 4; mt++) {
        int row = bm + warp_m * 64 + mt * 16 + g;       // global row (j0,j1)
        int b = row >> 11;
        int s0 = row & (SEQ - 1);                        // pos for j0,j1
        int s1 = (row + 8) & (SEQ - 1);                  // pos for j2,j3
        size_t base0 = ((size_t)(b * NH + h) * SEQ + s0) * DH;
        size_t base1 = ((size_t)(b * NH + h) * SEQ + s1) * DH;

        if (MODE == 1) {
            #pragma unroll
            for (int nt = 0; nt < 8; nt++) {
                int d = nt * 8 + t2;
                uint32_t hi0, lo0, hi1, lo1;
                split2(acc[mt][nt][0], acc[mt][nt][1], hi0, lo0);
                split2(acc[mt][nt][2], acc[mt][nt][3], hi1, lo1);
                *(uint32_t*)&Dh[base0 + d] = hi0;
                *(uint32_t*)&Dl[base0 + d] = lo0;
                *(uint32_t*)&Dh[base1 + d] = hi1;
                *(uint32_t*)&Dl[base1 + d] = lo1;
            }
        } else {  // MODE 0: RoPE
            #pragma unroll
            for (int nt = 0; nt < 4; nt++) {
                int i0 = nt * 8 + t2;                    // freq idx for j even
                // angles for (i0, i0+1) x (s0, s1)
                float e0 = (float)i0 * (1.0f / 32.0f);
                float e1 = (float)(i0 + 1) * (1.0f / 32.0f);
                float th0 = exp2f(-e0 * 19.931568569324174f);
                float th1 = exp2f(-e1 * 19.931568569324174f);
                float sn00 = sinf((float)s0 * th0), cs00 = cosf((float)s0 * th0);
                float sn01 = sinf((float)s0 * th1), cs01 = cosf((float)s0 * th1);
                float sn10 = sinf((float)s1 * th0), cs10 = cosf((float)s1 * th0);
                float sn11 = sinf((float)s1 * th1), cs11 = cosf((float)s1 * th1);

                float x10 = acc[mt][nt][0],     x20 = acc[mt][nt + 4][0];
                float x11 = acc[mt][nt][1],     x21 = acc[mt][nt + 4][1];
                float x12 = acc[mt][nt][2],     x22 = acc[mt][nt + 4][2];
                float x13 = acc[mt][nt][3],     x23 = acc[mt][nt + 4][3];

                float y10 = x10 * cs00 - x20 * sn00, y20 = x10 * sn00 + x20 * cs00;
                float y11 = x11 * cs01 - x21 * sn01, y21 = x11 * sn01 + x21 * cs01;
                float y12 = x12 * cs10 - x22 * sn10, y22 = x12 * sn10 + x22 * cs10;
                float y13 = x13 * cs11 - x23 * sn11, y23 = x13 * sn11 + x23 * cs11;

                uint32_t hi, lo;
                split2(y10, y11, hi, lo);
                *(uint32_t*)&Dh[base0 + i0] = hi;  *(uint32_t*)&Dl[base0 + i0] = lo;
                split2(y20, y21, hi, lo);
                *(uint32_t*)&Dh[base0 + i0 + 32] = hi;  *(uint32_t*)&Dl[base0 + i0 + 32] = lo;
                split2(y12, y13, hi, lo);
                *(uint32_t*)&Dh[base1 + i0] = hi;  *(uint32_t*)&Dl[base1 + i0] = lo;
                split2(y22, y23, hi, lo);
                *(uint32_t*)&Dh[base1 + i0 + 32] = hi;  *(uint32_t*)&Dl[base1 + i0 + 32] = lo;
            }
        }
    }
}

// ===========================================================================
// Flash attention via mma.sync, split-bf16. V in [bh][s][d] consumed via
// ldmatrix.trans. Output written as bf16 split (ah, al) directly.
// ===========================================================================
#define FP      144                 // smem row pitch (bytes)
#define FQ_OFF  0                   // Qh @0, Ql @18432 (128 rows x 144)
#define FK_OFF  36864               // + stage*18432; Kh +0, Kl +9216 (64x144)
#define FV_OFF  73728               // + stage*18432; Vh +0, Vl +9216 (64x144)
#define FL_SMEM 110592

__global__ __launch_bounds__(256) void flash_mma_kernel(
    const __nv_bfloat16* __restrict__ Qh_, const __nv_bfloat16* __restrict__ Ql_,
    const __nv_bfloat16* __restrict__ Kh_, const __nv_bfloat16* __restrict__ Kl_,
    const __nv_bfloat16* __restrict__ Vh_, const __nv_bfloat16* __restrict__ Vl_,
    __nv_bfloat16* __restrict__ Oh, __nv_bfloat16* __restrict__ Ol)
{
    extern __shared__ char smem[];
    uint32_t sb = smem_u32(smem);
    const int tid = threadIdx.x, lane = tid & 31, wid = tid >> 5;
    const int bh = blockIdx.y;
    const int qt = (gridDim.x - 1) - blockIdx.x;   // heavy tiles first
    const int nkt = 2 * (qt + 1);                  // 64-key chunks
    const size_t hoff = (size_t)bh * SEQ * DH;

    // Q tile load (once)
    {
        const __nv_bfloat16* qs[2] = {Qh_ + hoff, Ql_ + hoff};
        #pragma unroll
        for (int i = 0; i < 8; i++) {
            int idx = tid + i * 256;           // 0..2047
            int t = idx >> 10, rem = idx & 1023;
            int row = rem >> 3, c = rem & 7;
            cp_async16(sb + FQ_OFF + t * 18432 + row * FP + c * 16,
                       qs[t] + (size_t)(qt * 128 + row) * DH + c * 8);
        }
        cp_commit();
    }

    auto load_kv = [&](int kt, int s) {
        int k0 = kt * 64;
        const __nv_bfloat16* ks_[2] = {Kh_ + hoff, Kl_ + hoff};
        const __nv_bfloat16* vs_[2] = {Vh_ + hoff, Vl_ + hoff};
        #pragma unroll
        for (int i = 0; i < 4; i++) {
            int idx = tid + i * 256;           // 0..1023
            int t = idx >> 9, rem = idx & 511;
            int row = rem >> 3, c = rem & 7;
            cp_async16(sb + FK_OFF + s * 18432 + t * 9216 + row * FP + c * 16,
                       ks_[t] + (size_t)(k0 + row) * DH + c * 8);
        }
        #pragma unroll
        for (int i = 0; i < 4; i++) {
            int idx = tid + i * 256;
            int t = idx >> 9, rem = idx & 511;
            int row = rem >> 3, c = rem & 7;   // row = key idx, c = dh chunk
            cp_async16(sb + FV_OFF + s * 18432 + t * 9216 + row * FP + c * 16,
                       vs_[t] + (size_t)(k0 + row) * DH + c * 8);
        }
        cp_commit();
    };
    load_kv(0, 0);
    load_kv(1, 1);

    const int g = lane >> 2, t2 = (lane & 3) * 2;
    const int aRow = lane & 15, aK16 = (lane >> 4) * 16;
    const int bRow = (lane & 7) + ((lane >> 4) << 3);
    const int bK16 = ((lane >> 3) & 1) * 16;
    // trans-ldmatrix coords for V [key][dh]
    const int vRow = (lane & 7) + ((lane >> 3) & 1) * 8;  // key within 16-slab
    const int vC16 = (lane >> 4) * 16;                    // 8 dh = 16 bytes

    asm volatile("cp.async.wait_group 2;" ::: "memory");
    __syncthreads();

    // Q fragments resident: 4 k-steps x (hi, lo)
    uint32_t qh[4][4], ql[4][4];
    {
        uint32_t base = sb + FQ_OFF + (wid * 16 + aRow) * FP + aK16;
        #pragma unroll
        for (int ks = 0; ks < 4; ks++) {
            ldsm4(qh[ks], base + ks * 32);
            ldsm4(ql[ks], base + 18432 + ks * 32);
        }
    }

    float o[8][4];
    #pragma unroll
    for (int nt = 0; nt < 8; nt++)
        #pragma unroll
        for (int j = 0; j < 4; j++) o[nt][j] = 0.f;
    float l0 = 0.f, l1 = 0.f;
    const int row0 = qt * 128 + wid * 16 + g;

    for (int kt = 0; kt < nkt; kt++) {
        if (kt < nkt - 1) asm volatile("cp.async.wait_group 1;" ::: "memory");
        else              asm volatile("cp.async.wait_group 0;" ::: "memory");
        __syncthreads();

        uint32_t stK = sb + FK_OFF + (kt & 1) * 18432;
        uint32_t stV = sb + FV_OFF + (kt & 1) * 18432;

        // ---- S = Q K^T (3-way split) ----
        float S[8][4];
        #pragma unroll
        for (int nt = 0; nt < 8; nt++)
            #pragma unroll
            for (int j = 0; j < 4; j++) S[nt][j] = 0.f;

        #pragma unroll
        for (int ks = 0; ks < 4; ks++) {
            uint32_t fkh[4][4], fkl[4][4];
            #pragma unroll
            for (int n2 = 0; n2 < 4; n2++) {
                uint32_t a = stK + (n2 * 16 + bRow) * FP + bK16 + ks * 32;
                ldsm4(fkh[n2], a);
                ldsm4(fkl[n2], a + 9216);
            }
            #pragma unroll
            for (int nt = 0; nt < 8; nt++) {
                mma16816(S[nt], qh[ks], fkh[nt >> 1][(nt & 1) * 2], fkh[nt >> 1][(nt & 1) * 2 + 1]);
                mma16816(S[nt], qh[ks], fkl[nt >> 1][(nt & 1) * 2], fkl[nt >> 1][(nt & 1) * 2 + 1]);
                mma16816(S[nt], ql[ks], fkh[nt >> 1][(nt & 1) * 2], fkh[nt >> 1][(nt & 1) * 2 + 1]);
            }
        }

        // ---- softmax (no-max) + pack P into A-fragments ----
        uint32_t pah[4][4], pal[4][4];
        int k0 = kt * 64;
        #pragma unroll
        for (int nt = 0; nt < 8; nt++) {
            int col = k0 + nt * 8 + t2;
            float p0 = (col     <= row0)     ? __expf(S[nt][0] * 0.125f) : 0.f;
            float p1 = (col + 1 <= row0)     ? __expf(S[nt][1] * 0.125f) : 0.f;
            float p2 = (col     <= row0 + 8) ? __expf(S[nt][2] * 0.125f) : 0.f;
            float p3 = (col + 1 <= row0 + 8) ? __expf(S[nt][3] * 0.125f) : 0.f;
            l0 += p0 + p1;
            l1 += p2 + p3;
            __nv_bfloat16 h0 = __float2bfloat16(p0), h1 = __float2bfloat16(p1);
            __nv_bfloat16 h2 = __float2bfloat16(p2), h3 = __float2bfloat16(p3);
            float r0 = p0 - __bfloat162float(h0), r1 = p1 - __bfloat162float(h1);
            float r2 = p2 - __bfloat162float(h2), r3 = p3 - __bfloat162float(h3);
            int ks2 = nt >> 1, off = (nt & 1) * 2;
            pah[ks2][off]     = pack2h(h0, h1);
            pah[ks2][off + 1] = pack2h(h2, h3);
            pal[ks2][off]     = pack2f(r0, r1);
            pal[ks2][off + 1] = pack2f(r2, r3);
        }

        // ---- O += P V (3-way split), V [key][dh] via ldmatrix.trans ----
        #pragma unroll
        for (int ks2 = 0; ks2 < 4; ks2++) {
            uint32_t fvh[4][4], fvl[4][4];
            #pragma unroll
            for (int n2 = 0; n2 < 4; n2++) {
                uint32_t a = stV + (ks2 * 16 + vRow) * FP + n2 * 32 + vC16;
                ldsm4t(fvh[n2], a);
                ldsm4t(fvl[n2], a + 9216);
            }
            #pragma unroll
            for (int nt = 0; nt < 8; nt++) {
                mma16816(o[nt], pah[ks2], fvh[nt >> 1][(nt & 1) * 2], fvh[nt >> 1][(nt & 1) * 2 + 1]);
                mma16816(o[nt], pah[ks2], fvl[nt >> 1][(nt & 1) * 2], fvl[nt >> 1][(nt & 1) * 2 + 1]);
                mma16816(o[nt], pal[ks2], fvh[nt >> 1][(nt & 1) * 2], fvh[nt >> 1][(nt & 1) * 2 + 1]);
            }
        }

        __syncthreads();
        if (kt + 2 < nkt) load_kv(kt + 2, kt & 1);
    }

    // row-sum reduce within quads (lanes sharing g)
    l0 += __shfl_xor_sync(0xFFFFFFFFu, l0, 1);
    l0 += __shfl_xor_sync(0xFFFFFFFFu, l0, 2);
    l1 += __shfl_xor_sync(0xFFFFFFFFu, l1, 1);
    l1 += __shfl_xor_sync(0xFFFFFFFFu, l1, 2);
    float inv0 = 1.0f / l0, inv1 = 1.0f / l1;

    int b = bh >> 4, h = bh & 15;
    int srow = qt * 128 + wid * 16 + g;
    #pragma unroll
    for (int nt = 0; nt < 8; nt++) {
        int d = nt * 8 + t2;
        size_t o0 = (size_t)(b * SEQ + srow) * DIM + h * DH + d;
        size_t o1 = (size_t)(b * SEQ + srow + 8) * DIM + h * DH + d;
        uint32_t hi, lo;
        split2(o[nt][0] * inv0, o[nt][1] * inv0, hi, lo);
        *(uint32_t*)&Oh[o0] = hi;  *(uint32_t*)&Ol[o0] = lo;
        split2(o[nt][2] * inv1, o[nt][3] * inv1, hi, lo);
        *(uint32_t*)&Oh[o1] = hi;  *(uint32_t*)&Ol[o1] = lo;
    }
}

// ===========================================================================
// Launch
// ===========================================================================
extern "C" void kernel_launch(void* const* d_in, const int* in_sizes, int n_in,
                              void* d_out, int out_size)
{
    (void)in_sizes; (void)n_in; (void)out_size;
    const float* x  = (const float*)d_in[0];
    const float* ns = (const float*)d_in[1];
    const float* Wq = (const float*)d_in[2];
    const float* Wk = (const float*)d_in[3];
    const float* Wv = (const float*)d_in[4];
    const float* Wo = (const float*)d_in[5];
    float* out = (float*)d_out;

    __nv_bfloat16 *ah, *al, *th, *tl, *qh, *ql, *kh, *kl, *vh, *vl;
    cudaGetSymbolAddress((void**)&ah, g_ah);
    cudaGetSymbolAddress((void**)&al, g_al);
    cudaGetSymbolAddress((void**)&th, g_th);
    cudaGetSymbolAddress((void**)&tl, g_tl);
    cudaGetSymbolAddress((void**)&qh, g_qh);
    cudaGetSymbolAddress((void**)&ql, g_ql);
    cudaGetSymbolAddress((void**)&kh, g_kh);
    cudaGetSymbolAddress((void**)&kl, g_kl);
    cudaGetSymbolAddress((void**)&vh, g_vh);
    cudaGetSymbolAddress((void**)&vl, g_vl);

    cudaFuncSetAttribute(mma_gemm_kernel<0>,
                         cudaFuncAttributeMaxDynamicSharedMemorySize, GEMM_SMEM);
    cudaFuncSetAttribute(mma_gemm_kernel<1>,
                         cudaFuncAttributeMaxDynamicSharedMemorySize, GEMM_SMEM);
    cudaFuncSetAttribute(mma_gemm_kernel<2>,
                         cudaFuncAttributeMaxDynamicSharedMemorySize, GEMM_SMEM);
    cudaFuncSetAttribute(flash_mma_kernel,
                         cudaFuncAttributeMaxDynamicSharedMemorySize, FL_SMEM);

    rmsnorm_split_kernel<<<ROWS, 256>>>(x, ns, ah, al);

    dim3 gg(DIM / 128, ROWS / 256);   // (8, 16) = 128 blocks
    dim3 wg(DIM / 32, DIM / 32);      // (32, 32)

    wsplit_kernel<<<wg, 256>>>(Wq, th, tl);
    mma_gemm_kernel<0><<<gg, 256, GEMM_SMEM>>>(ah, al, th, tl, qh, ql, nullptr);
    wsplit_kernel<<<wg, 256>>>(Wk, th, tl);
    mma_gemm_kernel<0><<<gg, 256, GEMM_SMEM>>>(ah, al, th, tl, kh, kl, nullptr);
    wsplit_kernel<<<wg, 256>>>(Wv, th, tl);
    mma_gemm_kernel<1><<<gg, 256, GEMM_SMEM>>>(ah, al, th, tl, vh, vl, nullptr);

    flash_mma_kernel<<<dim3(SEQ / 128, BATCH * NH), 256, FL_SMEM>>>(
        qh, ql, kh, kl, vh, vl, ah, al);

    wsplit_kernel<<<wg, 256>>>(Wo, th, tl);
    mma_gemm_kernel<2><<<gg, 256, GEMM_SMEM>>>(ah, al, th, tl, nullptr, nullptr, out);
}

// round 7
// speedup vs baseline: 1.1328x; 1.1328x over previous
#include <cuda_runtime.h>
#include <cuda_bf16.h>
#include <stdint.h>
#include <math.h>

#define BATCH 2
#define SEQ   2048
#define DIM   1024
#define ROWS  (BATCH*SEQ)   // 4096
#define NH    16
#define DH    64

// Scratch (allocation-free rule: __device__ globals)
__device__ float g_qkv[3*ROWS*DIM];          // Q,K,V fp32 outputs
__device__ float g_ao[ROWS*DIM];
__device__ __nv_bfloat16 g_ah[ROWS*DIM];     // A split hi
__device__ __nv_bfloat16 g_al[ROWS*DIM];     // A split lo
__device__ __nv_bfloat16 g_th[4*DIM*DIM];    // W^T split hi [4][N][K] (q,k,v,o)
__device__ __nv_bfloat16 g_tl[4*DIM*DIM];    // W^T split lo
// attention operands, head-contiguous layouts
__device__ __nv_bfloat16 g_qh[ROWS*DIM];     // Q hi [bh][s][d]
__device__ __nv_bfloat16 g_ql[ROWS*DIM];
__device__ __nv_bfloat16 g_kh[ROWS*DIM];     // K hi [bh][s][d]
__device__ __nv_bfloat16 g_kl[ROWS*DIM];
__device__ __nv_bfloat16 g_vth[ROWS*DIM];    // V^T hi [bh][d][s]
__device__ __nv_bfloat16 g_vtl[ROWS*DIM];

// ===========================================================================
// Portable (compute_103-safe) PTX helpers: mma.sync / ldmatrix / cp.async
// ===========================================================================
__device__ __forceinline__ uint32_t smem_u32(const void* p) {
    uint32_t a;
    asm("{ .reg .u64 t; cvta.to.shared.u64 t, %1; cvt.u32.u64 %0, t; }"
        : "=r"(a) : "l"(p));
    return a;
}
__device__ __forceinline__ void cp_async16(uint32_t saddr, const void* gaddr) {
    asm volatile("cp.async.cg.shared.global [%0], [%1], 16;"
                 :: "r"(saddr), "l"(gaddr));
}
__device__ __forceinline__ void cp_commit() {
    asm volatile("cp.async.commit_group;" ::: "memory");
}
__device__ __forceinline__ void ldsm4(uint32_t* r, uint32_t addr) {
    asm volatile("ldmatrix.sync.aligned.m8n8.x4.shared.b16 {%0,%1,%2,%3}, [%4];"
                 : "=r"(r[0]), "=r"(r[1]), "=r"(r[2]), "=r"(r[3]) : "r"(addr));
}
__device__ __forceinline__ void mma16816(float* c, const uint32_t* a,
                                         uint32_t b0, uint32_t b1) {
    asm volatile(
        "mma.sync.aligned.m16n8k16.row.col.f32.bf16.bf16.f32 "
        "{%0,%1,%2,%3}, {%4,%5,%6,%7}, {%8,%9}, {%0,%1,%2,%3};"
        : "+f"(c[0]), "+f"(c[1]), "+f"(c[2]), "+f"(c[3])
        : "r"(a[0]), "r"(a[1]), "r"(a[2]), "r"(a[3]), "r"(b0), "r"(b1));
}
__device__ __forceinline__ uint32_t pack2h(__nv_bfloat16 a, __nv_bfloat16 b) {
    __nv_bfloat162 t = __halves2bfloat162(a, b);
    return *reinterpret_cast<uint32_t*>(&t);
}
__device__ __forceinline__ uint32_t pack2f(float a, float b) {
    __nv_bfloat162 t = __floats2bfloat162_rn(a, b);
    return *reinterpret_cast<uint32_t*>(&t);
}

// ===========================================================================
// RMSNorm fused with bf16 split: x -> (ah, al)
// ===========================================================================
__global__ __launch_bounds__(256) void rmsnorm_split_kernel(
    const float* __restrict__ x, const float* __restrict__ sc,
    __nv_bfloat16* __restrict__ hi, __nv_bfloat16* __restrict__ lo)
{
    int row = blockIdx.x;
    const float* xr = x + (size_t)row * DIM;
    float ss = 0.f;
    #pragma unroll
    for (int i = threadIdx.x; i < DIM; i += 256) {
        float v = xr[i];
        ss = fmaf(v, v, ss);
    }
    __shared__ float red[256];
    red[threadIdx.x] = ss;
    __syncthreads();
    #pragma unroll
    for (int s = 128; s > 0; s >>= 1) {
        if (threadIdx.x < s) red[threadIdx.x] += red[threadIdx.x + s];
        __syncthreads();
    }
    float r = rsqrtf(red[0] * (1.0f / DIM) + 1e-6f);
    #pragma unroll
    for (int i = threadIdx.x; i < DIM; i += 256) {
        float y = xr[i] * r * sc[i];
        __nv_bfloat16 h = __float2bfloat16(y);
        hi[(size_t)row * DIM + i] = h;
        lo[(size_t)row * DIM + i] = __float2bfloat16(y - __bfloat162float(h));
    }
}

// ===========================================================================
// Split fp32 -> bf16 (hi, lo). One thread per 4 elements.
// ===========================================================================
__global__ __launch_bounds__(256) void asplit_kernel(
    const float* __restrict__ x,
    __nv_bfloat16* __restrict__ hi, __nv_bfloat16* __restrict__ lo)
{
    int i = (blockIdx.x * 256 + threadIdx.x) * 4;
    float4 v = *(const float4*)(x + i);
    __nv_bfloat16 h0 = __float2bfloat16(v.x);
    __nv_bfloat16 h1 = __float2bfloat16(v.y);
    __nv_bfloat16 h2 = __float2bfloat16(v.z);
    __nv_bfloat16 h3 = __float2bfloat16(v.w);
    *(__nv_bfloat162*)(hi + i)     = __halves2bfloat162(h0, h1);
    *(__nv_bfloat162*)(hi + i + 2) = __halves2bfloat162(h2, h3);
    __nv_bfloat16 l0 = __float2bfloat16(v.x - __bfloat162float(h0));
    __nv_bfloat16 l1 = __float2bfloat16(v.y - __bfloat162float(h1));
    __nv_bfloat16 l2 = __float2bfloat16(v.z - __bfloat162float(h2));
    __nv_bfloat16 l3 = __float2bfloat16(v.w - __bfloat162float(h3));
    *(__nv_bfloat162*)(lo + i)     = __halves2bfloat162(l0, l1);
    *(__nv_bfloat162*)(lo + i + 2) = __halves2bfloat162(l2, l3);
}

// ===========================================================================
// Transpose + split for ALL FOUR weights in one launch.
// W[z] [K][N] fp32 -> (Th, Tl)[z] [N][K] bf16;  z = blockIdx.z in [0,4)
// ===========================================================================
__global__ __launch_bounds__(256) void wsplit4_kernel(
    const float* __restrict__ W0, const float* __restrict__ W1,
    const float* __restrict__ W2, const float* __restrict__ W3,
    __nv_bfloat16* __restrict__ Th, __nv_bfloat16* __restrict__ Tl)
{
    __shared__ float tile[32][33];
    int z = blockIdx.z;
    const float* W = (z == 0) ? W0 : (z == 1) ? W1 : (z == 2) ? W2 : W3;
    __nv_bfloat16* th = Th + (size_t)z * DIM * DIM;
    __nv_bfloat16* tl = Tl + (size_t)z * DIM * DIM;

    int k0 = blockIdx.y * 32, n0 = blockIdx.x * 32;
    int tx = threadIdx.x & 31, ty = threadIdx.x >> 5;   // 32 x 8
    #pragma unroll
    for (int i = 0; i < 32; i += 8)
        tile[ty + i][tx] = W[(size_t)(k0 + ty + i) * DIM + n0 + tx];
    __syncthreads();
    #pragma unroll
    for (int i = 0; i < 32; i += 8) {
        float v = tile[tx][ty + i];    // = W[k0+tx][n0+ty+i]
        __nv_bfloat16 h = __float2bfloat16(v);
        float r = v - __bfloat162float(h);
        size_t o = (size_t)(n0 + ty + i) * DIM + k0 + tx;
        th[o] = h;
        tl[o] = __float2bfloat16(r);
    }
}

// ===========================================================================
// bf16-split GEMM via mma.sync. Block tile 256x128, BK=32, 8 warps (4x2),
// warp tile 64x64. Supports NMAT weights in one launch: blockIdx.x's high
// bits select the weight and output slab.
// ===========================================================================
#define A_TILE_B 20480             // 256 rows x 80 bytes
#define B_TILE_B 10240             // 128 rows x 80 bytes
#define STG_B    (2*A_TILE_B + 2*B_TILE_B)   // 61440
#define GEMM_SMEM (2*STG_B)                   // 122880

__global__ __launch_bounds__(256) void mma_gemm_kernel(
    const __nv_bfloat16* __restrict__ Ah, const __nv_bfloat16* __restrict__ Al,
    const __nv_bfloat16* __restrict__ BhBase, const __nv_bfloat16* __restrict__ BlBase,
    float* __restrict__ CBase)
{
    extern __shared__ char smem[];
    uint32_t sb = smem_u32(smem);

    const int tid  = threadIdx.x;
    const int lane = tid & 31;
    const int wid  = tid >> 5;
    const int warp_m = wid & 3;
    const int warp_n = wid >> 2;
    const int which = blockIdx.x >> 3;               // weight index
    const int bm = blockIdx.y * 256;
    const int bn = (blockIdx.x & 7) * 128;

    const __nv_bfloat16* Bh = BhBase + (size_t)which * DIM * DIM;
    const __nv_bfloat16* Bl = BlBase + (size_t)which * DIM * DIM;
    float* C = CBase + (size_t)which * ROWS * DIM;

    float acc[4][8][4];
    #pragma unroll
    for (int i = 0; i < 4; i++)
        #pragma unroll
        for (int j = 0; j < 8; j++)
            #pragma unroll
            for (int q = 0; q < 4; q++) acc[i][j][q] = 0.f;

    auto load_stage = [&](int kt, int s) {
        const __nv_bfloat16* asrc[2] = {Ah, Al};
        #pragma unroll
        for (int t = 0; t < 2; t++) {
            #pragma unroll
            for (int i = 0; i < 4; i++) {
                int chunk = tid + i * 256;         // 0..1023
                int row = chunk >> 2, c = chunk & 3;
                cp_async16(sb + s * STG_B + t * A_TILE_B + row * 80 + c * 16,
                           asrc[t] + (size_t)(bm + row) * DIM + kt * 32 + c * 8);
            }
        }
        const __nv_bfloat16* bsrc[2] = {Bh, Bl};
        #pragma unroll
        for (int t = 0; t < 2; t++) {
            #pragma unroll
            for (int i = 0; i < 2; i++) {
                int chunk = tid + i * 256;         // 0..511
                int row = chunk >> 2, c = chunk & 3;
                cp_async16(sb + s * STG_B + 2 * A_TILE_B + t * B_TILE_B + row * 80 + c * 16,
                           bsrc[t] + (size_t)(bn + row) * DIM + kt * 32 + c * 8);
            }
        }
        cp_commit();
    };

    load_stage(0, 0);
    load_stage(1, 1);

    const int aRow = lane & 15;
    const int aK16 = (lane >> 4) * 16;
    const int bRow = (lane & 7) + ((lane >> 4) << 3);
    const int bK16 = ((lane >> 3) & 1) * 16;

    for (int kt = 0; kt < 32; kt++) {
        if (kt < 31) asm volatile("cp.async.wait_group 1;" ::: "memory");
        else         asm volatile("cp.async.wait_group 0;" ::: "memory");
        __syncthreads();

        uint32_t st  = sb + (kt & 1) * STG_B;
        uint32_t aHb = st + (warp_m * 64 + aRow) * 80 + aK16;
        uint32_t aLb = aHb + A_TILE_B;
        uint32_t bHb = st + 2 * A_TILE_B + (warp_n * 64 + bRow) * 80 + bK16;
        uint32_t bLb = bHb + B_TILE_B;

        #pragma unroll
        for (int ks = 0; ks < 2; ks++) {
            uint32_t koff = ks * 32;
            uint32_t fah[4][4], fal[4][4], fb[4][4];
            #pragma unroll
            for (int mt = 0; mt < 4; mt++) {
                ldsm4(fah[mt], aHb + mt * 1280 + koff);
                ldsm4(fal[mt], aLb + mt * 1280 + koff);
            }
            #pragma unroll
            for (int n2 = 0; n2 < 4; n2++)
                ldsm4(fb[n2], bHb + n2 * 1280 + koff);
            #pragma unroll
            for (int mt = 0; mt < 4; mt++)
                #pragma unroll
                for (int nt = 0; nt < 8; nt++)
                    mma16816(acc[mt][nt], fah[mt],
                             fb[nt >> 1][(nt & 1) * 2], fb[nt >> 1][(nt & 1) * 2 + 1]);
            #pragma unroll
            for (int mt = 0; mt < 4; mt++)
                #pragma unroll
                for (int nt = 0; nt < 8; nt++)
                    mma16816(acc[mt][nt], fal[mt],
                             fb[nt >> 1][(nt & 1) * 2], fb[nt >> 1][(nt & 1) * 2 + 1]);
            #pragma unroll
            for (int n2 = 0; n2 < 4; n2++)
                ldsm4(fb[n2], bLb + n2 * 1280 + koff);
            #pragma unroll
            for (int mt = 0; mt < 4; mt++)
                #pragma unroll
                for (int nt = 0; nt < 8; nt++)
                    mma16816(acc[mt][nt], fah[mt],
                             fb[nt >> 1][(nt & 1) * 2], fb[nt >> 1][(nt & 1) * 2 + 1]);
        }
        __syncthreads();
        if (kt + 2 < 32) load_stage(kt + 2, kt & 1);
    }

    const int g = lane >> 2, t2 = (lane & 3) * 2;
    #pragma unroll
    for (int mt = 0; mt < 4; mt++) {
        #pragma unroll
        for (int nt = 0; nt < 8; nt++) {
            int row = bm + warp_m * 64 + mt * 16 + g;
            int col = bn + warp_n * 64 + nt * 8 + t2;
            *(float2*)&C[(size_t)row * DIM + col] =
                make_float2(acc[mt][nt][0], acc[mt][nt][1]);
            *(float2*)&C[(size_t)(row + 8) * DIM + col] =
                make_float2(acc[mt][nt][2], acc[mt][nt][3]);
        }
    }
}

// ===========================================================================
// RoPE + split + relayout: q,k fp32 [row][h*64+d] -> bf16 hi/lo [bh][s][d]
// ===========================================================================
__global__ __launch_bounds__(256) void rope_split_kernel(
    const float* __restrict__ q, const float* __restrict__ k,
    __nv_bfloat16* __restrict__ Qh, __nv_bfloat16* __restrict__ Ql,
    __nv_bfloat16* __restrict__ Kh, __nv_bfloat16* __restrict__ Kl)
{
    int idx = blockIdx.x * 256 + threadIdx.x;   // 2^22 total
    int which = idx >> 21;
    int r   = idx & ((1 << 21) - 1);
    int row = r >> 9;
    int rem = r & 511;
    int head = rem >> 5;
    int i    = rem & 31;

    const float* src = (which ? k : q) + (size_t)row * DIM + head * DH;
    int pos = row & (SEQ - 1);

    float e = (2.0f * (float)i) / (float)DH;
    float theta = exp2f(-e * 19.931568569324174f);   // 1e6^-e
    float ang = (float)pos * theta;
    float sn = sinf(ang), cs = cosf(ang);

    float x1 = src[i], x2 = src[i + 32];
    float y1 = x1 * cs - x2 * sn;
    float y2 = x1 * sn + x2 * cs;

    int b = row >> 11, s = row & (SEQ - 1);
    size_t o = ((size_t)(b * NH + head) * SEQ + s) * DH + i;
    __nv_bfloat16 h1 = __float2bfloat16(y1);
    __nv_bfloat16 h2 = __float2bfloat16(y2);
    __nv_bfloat16* H = which ? Kh : Qh;
    __nv_bfloat16* L = which ? Kl : Ql;
    H[o]      = h1;
    H[o + 32] = h2;
    L[o]      = __float2bfloat16(y1 - __bfloat162float(h1));
    L[o + 32] = __float2bfloat16(y2 - __bfloat162float(h2));
}

// ===========================================================================
// V transpose + split: v fp32 [row][h*64+d] -> bf16 hi/lo [bh][d][s]
// ===========================================================================
__global__ __launch_bounds__(256) void vsplit_kernel(
    const float* __restrict__ v,
    __nv_bfloat16* __restrict__ Vth, __nv_bfloat16* __restrict__ Vtl)
{
    __shared__ float tile[32][33];
    int bh = blockIdx.z;
    int b = bh >> 4, h = bh & 15;
    int s0 = blockIdx.x * 32, d0 = blockIdx.y * 32;
    int tx = threadIdx.x & 31, ty = threadIdx.x >> 5;
    #pragma unroll
    for (int i = 0; i < 32; i += 8)
        tile[ty + i][tx] = v[(size_t)(b * SEQ + s0 + ty + i) * DIM + h * DH + d0 + tx];
    __syncthreads();
    #pragma unroll
    for (int i = 0; i < 32; i += 8) {
        float val = tile[tx][ty + i];   // = v[s0+tx][d0+ty+i]
        __nv_bfloat16 hh = __float2bfloat16(val);
        size_t o = ((size_t)(bh * DH + d0 + ty + i)) * SEQ + s0 + tx;
        Vth[o] = hh;
        Vtl[o] = __float2bfloat16(val - __bfloat162float(hh));
    }
}

// ===========================================================================
// Flash attention via mma.sync, split-bf16 throughout (validated round 4/5).
// ===========================================================================
#define FP      144                 // smem row pitch (bytes)
#define FQ_OFF  0                   // Qh @0, Ql @18432 (128 rows x 144)
#define FK_OFF  36864               // + stage*18432; Kh +0, Kl +9216 (64x144)
#define FV_OFF  73728               // + stage*18432; Vh +0, Vl +9216 (64x144)
#define FL_SMEM 110592

__global__ __launch_bounds__(256) void flash_mma_kernel(
    const __nv_bfloat16* __restrict__ Qh_, const __nv_bfloat16* __restrict__ Ql_,
    const __nv_bfloat16* __restrict__ Kh_, const __nv_bfloat16* __restrict__ Kl_,
    const __nv_bfloat16* __restrict__ Vth_, const __nv_bfloat16* __restrict__ Vtl_,
    float* __restrict__ ao)
{
    extern __shared__ char smem[];
    uint32_t sb = smem_u32(smem);
    const int tid = threadIdx.x, lane = tid & 31, wid = tid >> 5;
    const int bh = blockIdx.y;
    const int qt = (gridDim.x - 1) - blockIdx.x;   // heavy tiles first
    const int nkt = 2 * (qt + 1);                  // 64-key chunks
    const size_t qkoff = (size_t)bh * SEQ * DH;
    const size_t voff  = (size_t)bh * DH * SEQ;

    // Q tile load (once)
    {
        const __nv_bfloat16* qs[2] = {Qh_ + qkoff, Ql_ + qkoff};
        #pragma unroll
        for (int i = 0; i < 8; i++) {
            int idx = tid + i * 256;           // 0..2047
            int t = idx >> 10, rem = idx & 1023;
            int row = rem >> 3, c = rem & 7;
            cp_async16(sb + FQ_OFF + t * 18432 + row * FP + c * 16,
                       qs[t] + (size_t)(qt * 128 + row) * DH + c * 8);
        }
        cp_commit();
    }

    auto load_kv = [&](int kt, int s) {
        int k0 = kt * 64;
        const __nv_bfloat16* ks_[2] = {Kh_ + qkoff, Kl_ + qkoff};
        const __nv_bfloat16* vs_[2] = {Vth_ + voff, Vtl_ + voff};
        #pragma unroll
        for (int i = 0; i < 4; i++) {
            int idx = tid + i * 256;           // 0..1023
            int t = idx >> 9, rem = idx & 511;
            int row = rem >> 3, c = rem & 7;
            cp_async16(sb + FK_OFF + s * 18432 + t * 9216 + row * FP + c * 16,
                       ks_[t] + (size_t)(k0 + row) * DH + c * 8);
        }
        #pragma unroll
        for (int i = 0; i < 4; i++) {
            int idx = tid + i * 256;
            int t = idx >> 9, rem = idx & 511;
            int row = rem >> 3, c = rem & 7;   // row = dh index, c = key chunk
            cp_async16(sb + FV_OFF + s * 18432 + t * 9216 + row * FP + c * 16,
                       vs_[t] + (size_t)row * SEQ + k0 + c * 8);
        }
        cp_commit();
    };
    load_kv(0, 0);
    load_kv(1, 1);

    const int g = lane >> 2, t2 = (lane & 3) * 2;
    const int aRow = lane & 15, aK16 = (lane >> 4) * 16;
    const int bRow = (lane & 7) + ((lane >> 4) << 3);
    const int bK16 = ((lane >> 3) & 1) * 16;

    asm volatile("cp.async.wait_group 2;" ::: "memory");
    __syncthreads();

    // Q fragments resident: 4 k-steps x (hi, lo)
    uint32_t qh[4][4], ql[4][4];
    {
        uint32_t base = sb + FQ_OFF + (wid * 16 + aRow) * FP + aK16;
        #pragma unroll
        for (int ks = 0; ks < 4; ks++) {
            ldsm4(qh[ks], base + ks * 32);
            ldsm4(ql[ks], base + 18432 + ks * 32);
        }
    }

    float o[8][4];
    #pragma unroll
    for (int nt = 0; nt < 8; nt++)
        #pragma unroll
        for (int j = 0; j < 4; j++) o[nt][j] = 0.f;
    float l0 = 0.f, l1 = 0.f;
    const int row0 = qt * 128 + wid * 16 + g;

    for (int kt = 0; kt < nkt; kt++) {
        if (kt < nkt - 1) asm volatile("cp.async.wait_group 1;" ::: "memory");
        else              asm volatile("cp.async.wait_group 0;" ::: "memory");
        __syncthreads();

        uint32_t stK = sb + FK_OFF + (kt & 1) * 18432;
        uint32_t stV = sb + FV_OFF + (kt & 1) * 18432;

        // ---- S = Q K^T (3-way split) ----
        float S[8][4];
        #pragma unroll
        for (int nt = 0; nt < 8; nt++)
            #pragma unroll
            for (int j = 0; j < 4; j++) S[nt][j] = 0.f;

        #pragma unroll
        for (int ks = 0; ks < 4; ks++) {
            uint32_t fkh[4][4], fkl[4][4];
            #pragma unroll
            for (int n2 = 0; n2 < 4; n2++) {
                uint32_t a = stK + (n2 * 16 + bRow) * FP + bK16 + ks * 32;
                ldsm4(fkh[n2], a);
                ldsm4(fkl[n2], a + 9216);
            }
            #pragma unroll
            for (int nt = 0; nt < 8; nt++) {
                mma16816(S[nt], qh[ks], fkh[nt >> 1][(nt & 1) * 2], fkh[nt >> 1][(nt & 1) * 2 + 1]);
                mma16816(S[nt], qh[ks], fkl[nt >> 1][(nt & 1) * 2], fkl[nt >> 1][(nt & 1) * 2 + 1]);
                mma16816(S[nt], ql[ks], fkh[nt >> 1][(nt & 1) * 2], fkh[nt >> 1][(nt & 1) * 2 + 1]);
            }
        }

        // ---- softmax (no-max) + pack P into A-fragments ----
        uint32_t pah[4][4], pal[4][4];
        int k0 = kt * 64;
        #pragma unroll
        for (int nt = 0; nt < 8; nt++) {
            int col = k0 + nt * 8 + t2;
            float p0 = (col     <= row0)     ? __expf(S[nt][0] * 0.125f) : 0.f;
            float p1 = (col + 1 <= row0)     ? __expf(S[nt][1] * 0.125f) : 0.f;
            float p2 = (col     <= row0 + 8) ? __expf(S[nt][2] * 0.125f) : 0.f;
            float p3 = (col + 1 <= row0 + 8) ? __expf(S[nt][3] * 0.125f) : 0.f;
            l0 += p0 + p1;
            l1 += p2 + p3;
            __nv_bfloat16 h0 = __float2bfloat16(p0), h1 = __float2bfloat16(p1);
            __nv_bfloat16 h2 = __float2bfloat16(p2), h3 = __float2bfloat16(p3);
            float r0 = p0 - __bfloat162float(h0), r1 = p1 - __bfloat162float(h1);
            float r2 = p2 - __bfloat162float(h2), r3 = p3 - __bfloat162float(h3);
            int ks2 = nt >> 1, off = (nt & 1) * 2;
            pah[ks2][off]     = pack2h(h0, h1);
            pah[ks2][off + 1] = pack2h(h2, h3);
            pal[ks2][off]     = pack2f(r0, r1);
            pal[ks2][off + 1] = pack2f(r2, r3);
        }

        // ---- O += P V (3-way split), V^T in smem as [dh][key] ----
        #pragma unroll
        for (int ks2 = 0; ks2 < 4; ks2++) {
            uint32_t fvh[4][4], fvl[4][4];
            #pragma unroll
            for (int n2 = 0; n2 < 4; n2++) {
                uint32_t a = stV + (n2 * 16 + bRow) * FP + bK16 + ks2 * 32;
                ldsm4(fvh[n2], a);
                ldsm4(fvl[n2], a + 9216);
            }
            #pragma unroll
            for (int nt = 0; nt < 8; nt++) {
                mma16816(o[nt], pah[ks2], fvh[nt >> 1][(nt & 1) * 2], fvh[nt >> 1][(nt & 1) * 2 + 1]);
                mma16816(o[nt], pah[ks2], fvl[nt >> 1][(nt & 1) * 2], fvl[nt >> 1][(nt & 1) * 2 + 1]);
                mma16816(o[nt], pal[ks2], fvh[nt >> 1][(nt & 1) * 2], fvh[nt >> 1][(nt & 1) * 2 + 1]);
            }
        }

        __syncthreads();
        if (kt + 2 < nkt) load_kv(kt + 2, kt & 1);
    }

    // row-sum reduce within quads (lanes sharing g)
    l0 += __shfl_xor_sync(0xFFFFFFFFu, l0, 1);
    l0 += __shfl_xor_sync(0xFFFFFFFFu, l0, 2);
    l1 += __shfl_xor_sync(0xFFFFFFFFu, l1, 1);
    l1 += __shfl_xor_sync(0xFFFFFFFFu, l1, 2);
    float inv0 = 1.0f / l0, inv1 = 1.0f / l1;

    int b = bh >> 4, h = bh & 15;
    int srow = qt * 128 + wid * 16 + g;
    #pragma unroll
    for (int nt = 0; nt < 8; nt++) {
        int d = nt * 8 + t2;
        size_t o0 = (size_t)(b * SEQ + srow) * DIM + h * DH + d;
        size_t o1 = (size_t)(b * SEQ + srow + 8) * DIM + h * DH + d;
        *(float2*)&ao[o0] = make_float2(o[nt][0] * inv0, o[nt][1] * inv0);
        *(float2*)&ao[o1] = make_float2(o[nt][2] * inv1, o[nt][3] * inv1);
    }
}

// ===========================================================================
// Launch
// ===========================================================================
extern "C" void kernel_launch(void* const* d_in, const int* in_sizes, int n_in,
                              void* d_out, int out_size)
{
    (void)in_sizes; (void)n_in; (void)out_size;
    const float* x  = (const float*)d_in[0];
    const float* ns = (const float*)d_in[1];
    const float* Wq = (const float*)d_in[2];
    const float* Wk = (const float*)d_in[3];
    const float* Wv = (const float*)d_in[4];
    const float* Wo = (const float*)d_in[5];
    float* out = (float*)d_out;

    float *qkv, *ao;
    __nv_bfloat16 *ah, *al, *th, *tl, *qhp, *qlp, *khp, *klp, *vth, *vtl;
    cudaGetSymbolAddress((void**)&qkv, g_qkv);
    cudaGetSymbolAddress((void**)&ao, g_ao);
    cudaGetSymbolAddress((void**)&ah, g_ah);
    cudaGetSymbolAddress((void**)&al, g_al);
    cudaGetSymbolAddress((void**)&th, g_th);
    cudaGetSymbolAddress((void**)&tl, g_tl);
    cudaGetSymbolAddress((void**)&qhp, g_qh);
    cudaGetSymbolAddress((void**)&qlp, g_ql);
    cudaGetSymbolAddress((void**)&khp, g_kh);
    cudaGetSymbolAddress((void**)&klp, g_kl);
    cudaGetSymbolAddress((void**)&vth, g_vth);
    cudaGetSymbolAddress((void**)&vtl, g_vtl);

    cudaFuncSetAttribute(mma_gemm_kernel,
                         cudaFuncAttributeMaxDynamicSharedMemorySize, GEMM_SMEM);
    cudaFuncSetAttribute(flash_mma_kernel,
                         cudaFuncAttributeMaxDynamicSharedMemorySize, FL_SMEM);

    // All weight transposes in one launch; RMSNorm+split fused.
    wsplit4_kernel<<<dim3(DIM / 32, DIM / 32, 4), 256>>>(Wq, Wk, Wv, Wo, th, tl);
    rmsnorm_split_kernel<<<ROWS, 256>>>(x, ns, ah, al);

    // Q, K, V projections in ONE launch (grid.x covers 3 weights)
    mma_gemm_kernel<<<dim3(3 * (DIM / 128), ROWS / 256), 256, GEMM_SMEM>>>(
        ah, al, th, tl, qkv);

    rope_split_kernel<<<(2 * ROWS * NH * 32) / 256, 256>>>(
        qkv, qkv + ROWS * DIM, qhp, qlp, khp, klp);
    vsplit_kernel<<<dim3(SEQ / 32, DH / 32, BATCH * NH), 256>>>(
        qkv + 2 * ROWS * DIM, vth, vtl);

    flash_mma_kernel<<<dim3(SEQ / 128, BATCH * NH), 256, FL_SMEM>>>(
        qhp, qlp, khp, klp, vth, vtl, ao);

    asplit_kernel<<<(ROWS * DIM) / (256 * 4), 256>>>(ao, ah, al);
    // Output projection: weight index 3 (pass shifted bases, grid.x = 8)
    mma_gemm_kernel<<<dim3(DIM / 128, ROWS / 256), 256, GEMM_SMEM>>>(
        ah, al, th + (size_t)3 * DIM * DIM, tl + (size_t)3 * DIM * DIM, out);
}

// round 8
// speedup vs baseline: 1.1427x; 1.0087x over previous
#include <cuda_runtime.h>
#include <cuda_bf16.h>
#include <stdint.h>
#include <math.h>

#define BATCH 2
#define SEQ   2048
#define DIM   1024
#define ROWS  (BATCH*SEQ)   // 4096
#define NH    16
#define DH    64

// Scratch (allocation-free rule: __device__ globals)
__device__ float g_qkv[3*ROWS*DIM];          // Q,K,V fp32 outputs
__device__ float g_ao[ROWS*DIM];
__device__ float g_sinT[SEQ*32];             // RoPE tables [pos][i]
__device__ float g_cosT[SEQ*32];
__device__ __nv_bfloat16 g_ah[ROWS*DIM];     // A split hi
__device__ __nv_bfloat16 g_al[ROWS*DIM];     // A split lo
__device__ __nv_bfloat16 g_th[4*DIM*DIM];    // W^T split hi [4][N][K] (q,k,v,o)
__device__ __nv_bfloat16 g_tl[4*DIM*DIM];    // W^T split lo
// attention operands, head-contiguous layouts
__device__ __nv_bfloat16 g_qh[ROWS*DIM];     // Q hi [bh][s][d]
__device__ __nv_bfloat16 g_ql[ROWS*DIM];
__device__ __nv_bfloat16 g_kh[ROWS*DIM];     // K hi [bh][s][d]
__device__ __nv_bfloat16 g_kl[ROWS*DIM];
__device__ __nv_bfloat16 g_vth[ROWS*DIM];    // V^T hi [bh][d][s]
__device__ __nv_bfloat16 g_vtl[ROWS*DIM];

// ===========================================================================
// Portable (compute_103-safe) PTX helpers: mma.sync / ldmatrix / cp.async
// ===========================================================================
__device__ __forceinline__ uint32_t smem_u32(const void* p) {
    uint32_t a;
    asm("{ .reg .u64 t; cvta.to.shared.u64 t, %1; cvt.u32.u64 %0, t; }"
        : "=r"(a) : "l"(p));
    return a;
}
__device__ __forceinline__ void cp_async16(uint32_t saddr, const void* gaddr) {
    asm volatile("cp.async.cg.shared.global [%0], [%1], 16;"
                 :: "r"(saddr), "l"(gaddr));
}
__device__ __forceinline__ void cp_commit() {
    asm volatile("cp.async.commit_group;" ::: "memory");
}
__device__ __forceinline__ void ldsm4(uint32_t* r, uint32_t addr) {
    asm volatile("ldmatrix.sync.aligned.m8n8.x4.shared.b16 {%0,%1,%2,%3}, [%4];"
                 : "=r"(r[0]), "=r"(r[1]), "=r"(r[2]), "=r"(r[3]) : "r"(addr));
}
__device__ __forceinline__ void mma16816(float* c, const uint32_t* a,
                                         uint32_t b0, uint32_t b1) {
    asm volatile(
        "mma.sync.aligned.m16n8k16.row.col.f32.bf16.bf16.f32 "
        "{%0,%1,%2,%3}, {%4,%5,%6,%7}, {%8,%9}, {%0,%1,%2,%3};"
        : "+f"(c[0]), "+f"(c[1]), "+f"(c[2]), "+f"(c[3])
        : "r"(a[0]), "r"(a[1]), "r"(a[2]), "r"(a[3]), "r"(b0), "r"(b1));
}
__device__ __forceinline__ uint32_t pack2h(__nv_bfloat16 a, __nv_bfloat16 b) {
    __nv_bfloat162 t = __halves2bfloat162(a, b);
    return *reinterpret_cast<uint32_t*>(&t);
}
__device__ __forceinline__ uint32_t pack2f(float a, float b) {
    __nv_bfloat162 t = __floats2bfloat162_rn(a, b);
    return *reinterpret_cast<uint32_t*>(&t);
}
__device__ __forceinline__ void split2(float a, float b, uint32_t& hi, uint32_t& lo) {
    __nv_bfloat16 ha = __float2bfloat16(a), hb = __float2bfloat16(b);
    hi = pack2h(ha, hb);
    lo = pack2f(a - __bfloat162float(ha), b - __bfloat162float(hb));
}

// ===========================================================================
// RoPE table: sin/cos for all (pos, i). 64K entries.
// ===========================================================================
__global__ __launch_bounds__(256) void rope_table_kernel(
    float* __restrict__ sinT, float* __restrict__ cosT)
{
    int idx = blockIdx.x * 256 + threadIdx.x;   // 65536
    int pos = idx >> 5, i = idx & 31;
    float e = (2.0f * (float)i) / (float)DH;
    float theta = exp2f(-e * 19.931568569324174f);   // 1e6^-e
    float ang = (float)pos * theta;
    sinT[idx] = sinf(ang);
    cosT[idx] = cosf(ang);
}

// ===========================================================================
// RMSNorm fused with bf16 split: x -> (ah, al). x cached in registers.
// ===========================================================================
__global__ __launch_bounds__(256) void rmsnorm_split_kernel(
    const float* __restrict__ x, const float* __restrict__ sc,
    __nv_bfloat16* __restrict__ hi, __nv_bfloat16* __restrict__ lo)
{
    int row = blockIdx.x;
    const float* xr = x + (size_t)row * DIM;
    float v[4];
    float ss = 0.f;
    #pragma unroll
    for (int j = 0; j < 4; j++) {
        v[j] = xr[threadIdx.x + j * 256];
        ss = fmaf(v[j], v[j], ss);
    }
    __shared__ float red[256];
    red[threadIdx.x] = ss;
    __syncthreads();
    #pragma unroll
    for (int s = 128; s > 0; s >>= 1) {
        if (threadIdx.x < s) red[threadIdx.x] += red[threadIdx.x + s];
        __syncthreads();
    }
    float r = rsqrtf(red[0] * (1.0f / DIM) + 1e-6f);
    #pragma unroll
    for (int j = 0; j < 4; j++) {
        int i = threadIdx.x + j * 256;
        float y = v[j] * r * sc[i];
        __nv_bfloat16 h = __float2bfloat16(y);
        hi[(size_t)row * DIM + i] = h;
        lo[(size_t)row * DIM + i] = __float2bfloat16(y - __bfloat162float(h));
    }
}

// ===========================================================================
// Split fp32 -> bf16 (hi, lo). One thread per 4 elements.
// ===========================================================================
__global__ __launch_bounds__(256) void asplit_kernel(
    const float* __restrict__ x,
    __nv_bfloat16* __restrict__ hi, __nv_bfloat16* __restrict__ lo)
{
    int i = (blockIdx.x * 256 + threadIdx.x) * 4;
    float4 v = *(const float4*)(x + i);
    __nv_bfloat16 h0 = __float2bfloat16(v.x);
    __nv_bfloat16 h1 = __float2bfloat16(v.y);
    __nv_bfloat16 h2 = __float2bfloat16(v.z);
    __nv_bfloat16 h3 = __float2bfloat16(v.w);
    *(__nv_bfloat162*)(hi + i)     = __halves2bfloat162(h0, h1);
    *(__nv_bfloat162*)(hi + i + 2) = __halves2bfloat162(h2, h3);
    __nv_bfloat16 l0 = __float2bfloat16(v.x - __bfloat162float(h0));
    __nv_bfloat16 l1 = __float2bfloat16(v.y - __bfloat162float(h1));
    __nv_bfloat16 l2 = __float2bfloat16(v.z - __bfloat162float(h2));
    __nv_bfloat16 l3 = __float2bfloat16(v.w - __bfloat162float(h3));
    *(__nv_bfloat162*)(lo + i)     = __halves2bfloat162(l0, l1);
    *(__nv_bfloat162*)(lo + i + 2) = __halves2bfloat162(l2, l3);
}

// ===========================================================================
// Transpose + split for ALL FOUR weights in one launch.
// ===========================================================================
__global__ __launch_bounds__(256) void wsplit4_kernel(
    const float* __restrict__ W0, const float* __restrict__ W1,
    const float* __restrict__ W2, const float* __restrict__ W3,
    __nv_bfloat16* __restrict__ Th, __nv_bfloat16* __restrict__ Tl)
{
    __shared__ float tile[32][33];
    int z = blockIdx.z;
    const float* W = (z == 0) ? W0 : (z == 1) ? W1 : (z == 2) ? W2 : W3;
    __nv_bfloat16* th = Th + (size_t)z * DIM * DIM;
    __nv_bfloat16* tl = Tl + (size_t)z * DIM * DIM;

    int k0 = blockIdx.y * 32, n0 = blockIdx.x * 32;
    int tx = threadIdx.x & 31, ty = threadIdx.x >> 5;   // 32 x 8
    #pragma unroll
    for (int i = 0; i < 32; i += 8)
        tile[ty + i][tx] = W[(size_t)(k0 + ty + i) * DIM + n0 + tx];
    __syncthreads();
    #pragma unroll
    for (int i = 0; i < 32; i += 8) {
        float v = tile[tx][ty + i];    // = W[k0+tx][n0+ty+i]
        __nv_bfloat16 h = __float2bfloat16(v);
        float r = v - __bfloat162float(h);
        size_t o = (size_t)(n0 + ty + i) * DIM + k0 + tx;
        th[o] = h;
        tl[o] = __float2bfloat16(r);
    }
}

// ===========================================================================
// bf16-split GEMM via mma.sync (validated rounds 5-7, unchanged).
// ===========================================================================
#define A_TILE_B 20480             // 256 rows x 80 bytes
#define B_TILE_B 10240             // 128 rows x 80 bytes
#define STG_B    (2*A_TILE_B + 2*B_TILE_B)   // 61440
#define GEMM_SMEM (2*STG_B)                   // 122880

__global__ __launch_bounds__(256) void mma_gemm_kernel(
    const __nv_bfloat16* __restrict__ Ah, const __nv_bfloat16* __restrict__ Al,
    const __nv_bfloat16* __restrict__ BhBase, const __nv_bfloat16* __restrict__ BlBase,
    float* __restrict__ CBase)
{
    extern __shared__ char smem[];
    uint32_t sb = smem_u32(smem);

    const int tid  = threadIdx.x;
    const int lane = tid & 31;
    const int wid  = tid >> 5;
    const int warp_m = wid & 3;
    const int warp_n = wid >> 2;
    const int which = blockIdx.x >> 3;               // weight index
    const int bm = blockIdx.y * 256;
    const int bn = (blockIdx.x & 7) * 128;

    const __nv_bfloat16* Bh = BhBase + (size_t)which * DIM * DIM;
    const __nv_bfloat16* Bl = BlBase + (size_t)which * DIM * DIM;
    float* C = CBase + (size_t)which * ROWS * DIM;

    float acc[4][8][4];
    #pragma unroll
    for (int i = 0; i < 4; i++)
        #pragma unroll
        for (int j = 0; j < 8; j++)
            #pragma unroll
            for (int q = 0; q < 4; q++) acc[i][j][q] = 0.f;

    auto load_stage = [&](int kt, int s) {
        const __nv_bfloat16* asrc[2] = {Ah, Al};
        #pragma unroll
        for (int t = 0; t < 2; t++) {
            #pragma unroll
            for (int i = 0; i < 4; i++) {
                int chunk = tid + i * 256;         // 0..1023
                int row = chunk >> 2, c = chunk & 3;
                cp_async16(sb + s * STG_B + t * A_TILE_B + row * 80 + c * 16,
                           asrc[t] + (size_t)(bm + row) * DIM + kt * 32 + c * 8);
            }
        }
        const __nv_bfloat16* bsrc[2] = {Bh, Bl};
        #pragma unroll
        for (int t = 0; t < 2; t++) {
            #pragma unroll
            for (int i = 0; i < 2; i++) {
                int chunk = tid + i * 256;         // 0..511
                int row = chunk >> 2, c = chunk & 3;
                cp_async16(sb + s * STG_B + 2 * A_TILE_B + t * B_TILE_B + row * 80 + c * 16,
                           bsrc[t] + (size_t)(bn + row) * DIM + kt * 32 + c * 8);
            }
        }
        cp_commit();
    };

    load_stage(0, 0);
    load_stage(1, 1);

    const int aRow = lane & 15;
    const int aK16 = (lane >> 4) * 16;
    const int bRow = (lane & 7) + ((lane >> 4) << 3);
    const int bK16 = ((lane >> 3) & 1) * 16;

    for (int kt = 0; kt < 32; kt++) {
        if (kt < 31) asm volatile("cp.async.wait_group 1;" ::: "memory");
        else         asm volatile("cp.async.wait_group 0;" ::: "memory");
        __syncthreads();

        uint32_t st  = sb + (kt & 1) * STG_B;
        uint32_t aHb = st + (warp_m * 64 + aRow) * 80 + aK16;
        uint32_t aLb = aHb + A_TILE_B;
        uint32_t bHb = st + 2 * A_TILE_B + (warp_n * 64 + bRow) * 80 + bK16;
        uint32_t bLb = bHb + B_TILE_B;

        #pragma unroll
        for (int ks = 0; ks < 2; ks++) {
            uint32_t koff = ks * 32;
            uint32_t fah[4][4], fal[4][4], fb[4][4];
            #pragma unroll
            for (int mt = 0; mt < 4; mt++) {
                ldsm4(fah[mt], aHb + mt * 1280 + koff);
                ldsm4(fal[mt], aLb + mt * 1280 + koff);
            }
            #pragma unroll
            for (int n2 = 0; n2 < 4; n2++)
                ldsm4(fb[n2], bHb + n2 * 1280 + koff);
            #pragma unroll
            for (int mt = 0; mt < 4; mt++)
                #pragma unroll
                for (int nt = 0; nt < 8; nt++)
                    mma16816(acc[mt][nt], fah[mt],
                             fb[nt >> 1][(nt & 1) * 2], fb[nt >> 1][(nt & 1) * 2 + 1]);
            #pragma unroll
            for (int mt = 0; mt < 4; mt++)
                #pragma unroll
                for (int nt = 0; nt < 8; nt++)
                    mma16816(acc[mt][nt], fal[mt],
                             fb[nt >> 1][(nt & 1) * 2], fb[nt >> 1][(nt & 1) * 2 + 1]);
            #pragma unroll
            for (int n2 = 0; n2 < 4; n2++)
                ldsm4(fb[n2], bLb + n2 * 1280 + koff);
            #pragma unroll
            for (int mt = 0; mt < 4; mt++)
                #pragma unroll
                for (int nt = 0; nt < 8; nt++)
                    mma16816(acc[mt][nt], fah[mt],
                             fb[nt >> 1][(nt & 1) * 2], fb[nt >> 1][(nt & 1) * 2 + 1]);
        }
        __syncthreads();
        if (kt + 2 < 32) load_stage(kt + 2, kt & 1);
    }

    const int g = lane >> 2, t2 = (lane & 3) * 2;
    #pragma unroll
    for (int mt = 0; mt < 4; mt++) {
        #pragma unroll
        for (int nt = 0; nt < 8; nt++) {
            int row = bm + warp_m * 64 + mt * 16 + g;
            int col = bn + warp_n * 64 + nt * 8 + t2;
            *(float2*)&C[(size_t)row * DIM + col] =
                make_float2(acc[mt][nt][0], acc[mt][nt][1]);
            *(float2*)&C[(size_t)(row + 8) * DIM + col] =
                make_float2(acc[mt][nt][2], acc[mt][nt][3]);
        }
    }
}

// ===========================================================================
// RoPE + split + relayout, table-driven, fully vectorized.
// One thread handles 2 adjacent freq indices (i, i+1) of one (tensor,row,head).
// ===========================================================================
__global__ __launch_bounds__(256) void rope_split_kernel(
    const float* __restrict__ q, const float* __restrict__ k,
    const float* __restrict__ sinT, const float* __restrict__ cosT,
    __nv_bfloat16* __restrict__ Qh, __nv_bfloat16* __restrict__ Ql,
    __nv_bfloat16* __restrict__ Kh, __nv_bfloat16* __restrict__ Kl)
{
    int idx = blockIdx.x * 256 + threadIdx.x;   // 2^21 total
    int which = idx >> 20;
    int r   = idx & ((1 << 20) - 1);
    int row = r >> 8;
    int rem = r & 255;
    int head = rem >> 4;
    int i    = (rem & 15) * 2;

    const float* src = (which ? k : q) + (size_t)row * DIM + head * DH;
    int pos = row & (SEQ - 1);

    float2 sn = *(const float2*)&sinT[pos * 32 + i];
    float2 cs = *(const float2*)&cosT[pos * 32 + i];
    float2 x1 = *(const float2*)&src[i];
    float2 x2 = *(const float2*)&src[i + 32];

    float y1a = x1.x * cs.x - x2.x * sn.x, y2a = x1.x * sn.x + x2.x * cs.x;
    float y1b = x1.y * cs.y - x2.y * sn.y, y2b = x1.y * sn.y + x2.y * cs.y;

    int b = row >> 11, s = row & (SEQ - 1);
    size_t o = ((size_t)(b * NH + head) * SEQ + s) * DH + i;
    __nv_bfloat16* H = which ? Kh : Qh;
    __nv_bfloat16* L = which ? Kl : Ql;
    uint32_t hi, lo;
    split2(y1a, y1b, hi, lo);
    *(uint32_t*)&H[o] = hi;       *(uint32_t*)&L[o] = lo;
    split2(y2a, y2b, hi, lo);
    *(uint32_t*)&H[o + 32] = hi;  *(uint32_t*)&L[o + 32] = lo;
}

// ===========================================================================
// V transpose + split: v fp32 [row][h*64+d] -> bf16 hi/lo [bh][d][s]
// ===========================================================================
__global__ __launch_bounds__(256) void vsplit_kernel(
    const float* __restrict__ v,
    __nv_bfloat16* __restrict__ Vth, __nv_bfloat16* __restrict__ Vtl)
{
    __shared__ float tile[32][33];
    int bh = blockIdx.z;
    int b = bh >> 4, h = bh & 15;
    int s0 = blockIdx.x * 32, d0 = blockIdx.y * 32;
    int tx = threadIdx.x & 31, ty = threadIdx.x >> 5;
    #pragma unroll
    for (int i = 0; i < 32; i += 8)
        tile[ty + i][tx] = v[(size_t)(b * SEQ + s0 + ty + i) * DIM + h * DH + d0 + tx];
    __syncthreads();
    #pragma unroll
    for (int i = 0; i < 32; i += 8) {
        float val = tile[tx][ty + i];   // = v[s0+tx][d0+ty+i]
        __nv_bfloat16 hh = __float2bfloat16(val);
        size_t o = ((size_t)(bh * DH + d0 + ty + i)) * SEQ + s0 + tx;
        Vth[o] = hh;
        Vtl[o] = __float2bfloat16(val - __bfloat162float(hh));
    }
}

// ===========================================================================
// Flash attention via mma.sync, split-bf16 (validated rounds 4-7, unchanged).
// ===========================================================================
#define FP      144                 // smem row pitch (bytes)
#define FQ_OFF  0
#define FK_OFF  36864
#define FV_OFF  73728
#define FL_SMEM 110592

__global__ __launch_bounds__(256) void flash_mma_kernel(
    const __nv_bfloat16* __restrict__ Qh_, const __nv_bfloat16* __restrict__ Ql_,
    const __nv_bfloat16* __restrict__ Kh_, const __nv_bfloat16* __restrict__ Kl_,
    const __nv_bfloat16* __restrict__ Vth_, const __nv_bfloat16* __restrict__ Vtl_,
    float* __restrict__ ao)
{
    extern __shared__ char smem[];
    uint32_t sb = smem_u32(smem);
    const int tid = threadIdx.x, lane = tid & 31, wid = tid >> 5;
    const int bh = blockIdx.y;
    const int qt = (gridDim.x - 1) - blockIdx.x;   // heavy tiles first
    const int nkt = 2 * (qt + 1);                  // 64-key chunks
    const size_t qkoff = (size_t)bh * SEQ * DH;
    const size_t voff  = (size_t)bh * DH * SEQ;

    // Q tile load (once)
    {
        const __nv_bfloat16* qs[2] = {Qh_ + qkoff, Ql_ + qkoff};
        #pragma unroll
        for (int i = 0; i < 8; i++) {
            int idx = tid + i * 256;           // 0..2047
            int t = idx >> 10, rem = idx & 1023;
            int row = rem >> 3, c = rem & 7;
            cp_async16(sb + FQ_OFF + t * 18432 + row * FP + c * 16,
                       qs[t] + (size_t)(qt * 128 + row) * DH + c * 8);
        }
        cp_commit();
    }

    auto load_kv = [&](int kt, int s) {
        int k0 = kt * 64;
        const __nv_bfloat16* ks_[2] = {Kh_ + qkoff, Kl_ + qkoff};
        const __nv_bfloat16* vs_[2] = {Vth_ + voff, Vtl_ + voff};
        #pragma unroll
        for (int i = 0; i < 4; i++) {
            int idx = tid + i * 256;           // 0..1023
            int t = idx >> 9, rem = idx & 511;
            int row = rem >> 3, c = rem & 7;
            cp_async16(sb + FK_OFF + s * 18432 + t * 9216 + row * FP + c * 16,
                       ks_[t] + (size_t)(k0 + row) * DH + c * 8);
        }
        #pragma unroll
        for (int i = 0; i < 4; i++) {
            int idx = tid + i * 256;
            int t = idx >> 9, rem = idx & 511;
            int row = rem >> 3, c = rem & 7;   // row = dh index, c = key chunk
            cp_async16(sb + FV_OFF + s * 18432 + t * 9216 + row * FP + c * 16,
                       vs_[t] + (size_t)row * SEQ + k0 + c * 8);
        }
        cp_commit();
    };
    load_kv(0, 0);
    load_kv(1, 1);

    const int g = lane >> 2, t2 = (lane & 3) * 2;
    const int aRow = lane & 15, aK16 = (lane >> 4) * 16;
    const int bRow = (lane & 7) + ((lane >> 4) << 3);
    const int bK16 = ((lane >> 3) & 1) * 16;

    asm volatile("cp.async.wait_group 2;" ::: "memory");
    __syncthreads();

    uint32_t qh[4][4], ql[4][4];
    {
        uint32_t base = sb + FQ_OFF + (wid * 16 + aRow) * FP + aK16;
        #pragma unroll
        for (int ks = 0; ks < 4; ks++) {
            ldsm4(qh[ks], base + ks * 32);
            ldsm4(ql[ks], base + 18432 + ks * 32);
        }
    }

    float o[8][4];
    #pragma unroll
    for (int nt = 0; nt < 8; nt++)
        #pragma unroll
        for (int j = 0; j < 4; j++) o[nt][j] = 0.f;
    float l0 = 0.f, l1 = 0.f;
    const int row0 = qt * 128 + wid * 16 + g;

    for (int kt = 0; kt < nkt; kt++) {
        if (kt < nkt - 1) asm volatile("cp.async.wait_group 1;" ::: "memory");
        else              asm volatile("cp.async.wait_group 0;" ::: "memory");
        __syncthreads();

        uint32_t stK = sb + FK_OFF + (kt & 1) * 18432;
        uint32_t stV = sb + FV_OFF + (kt & 1) * 18432;

        float S[8][4];
        #pragma unroll
        for (int nt = 0; nt < 8; nt++)
            #pragma unroll
            for (int j = 0; j < 4; j++) S[nt][j] = 0.f;

        #pragma unroll
        for (int ks = 0; ks < 4; ks++) {
            uint32_t fkh[4][4], fkl[4][4];
            #pragma unroll
            for (int n2 = 0; n2 < 4; n2++) {
                uint32_t a = stK + (n2 * 16 + bRow) * FP + bK16 + ks * 32;
                ldsm4(fkh[n2], a);
                ldsm4(fkl[n2], a + 9216);
            }
            #pragma unroll
            for (int nt = 0; nt < 8; nt++) {
                mma16816(S[nt], qh[ks], fkh[nt >> 1][(nt & 1) * 2], fkh[nt >> 1][(nt & 1) * 2 + 1]);
                mma16816(S[nt], qh[ks], fkl[nt >> 1][(nt & 1) * 2], fkl[nt >> 1][(nt & 1) * 2 + 1]);
                mma16816(S[nt], ql[ks], fkh[nt >> 1][(nt & 1) * 2], fkh[nt >> 1][(nt & 1) * 2 + 1]);
            }
        }

        uint32_t pah[4][4], pal[4][4];
        int k0 = kt * 64;
        #pragma unroll
        for (int nt = 0; nt < 8; nt++) {
            int col = k0 + nt * 8 + t2;
            float p0 = (col     <= row0)     ? __expf(S[nt][0] * 0.125f) : 0.f;
            float p1 = (col + 1 <= row0)     ? __expf(S[nt][1] * 0.125f) : 0.f;
            float p2 = (col     <= row0 + 8) ? __expf(S[nt][2] * 0.125f) : 0.f;
            float p3 = (col + 1 <= row0 + 8) ? __expf(S[nt][3] * 0.125f) : 0.f;
            l0 += p0 + p1;
            l1 += p2 + p3;
            __nv_bfloat16 h0 = __float2bfloat16(p0), h1 = __float2bfloat16(p1);
            __nv_bfloat16 h2 = __float2bfloat16(p2), h3 = __float2bfloat16(p3);
            float r0 = p0 - __bfloat162float(h0), r1 = p1 - __bfloat162float(h1);
            float r2 = p2 - __bfloat162float(h2), r3 = p3 - __bfloat162float(h3);
            int ks2 = nt >> 1, off = (nt & 1) * 2;
            pah[ks2][off]     = pack2h(h0, h1);
            pah[ks2][off + 1] = pack2h(h2, h3);
            pal[ks2][off]     = pack2f(r0, r1);
            pal[ks2][off + 1] = pack2f(r2, r3);
        }

        #pragma unroll
        for (int ks2 = 0; ks2 < 4; ks2++) {
            uint32_t fvh[4][4], fvl[4][4];
            #pragma unroll
            for (int n2 = 0; n2 < 4; n2++) {
                uint32_t a = stV + (n2 * 16 + bRow) * FP + bK16 + ks2 * 32;
                ldsm4(fvh[n2], a);
                ldsm4(fvl[n2], a + 9216);
            }
            #pragma unroll
            for (int nt = 0; nt < 8; nt++) {
                mma16816(o[nt], pah[ks2], fvh[nt >> 1][(nt & 1) * 2], fvh[nt >> 1][(nt & 1) * 2 + 1]);
                mma16816(o[nt], pah[ks2], fvl[nt >> 1][(nt & 1) * 2], fvl[nt >> 1][(nt & 1) * 2 + 1]);
                mma16816(o[nt], pal[ks2], fvh[nt >> 1][(nt & 1) * 2], fvh[nt >> 1][(nt & 1) * 2 + 1]);
            }
        }

        __syncthreads();
        if (kt + 2 < nkt) load_kv(kt + 2, kt & 1);
    }

    l0 += __shfl_xor_sync(0xFFFFFFFFu, l0, 1);
    l0 += __shfl_xor_sync(0xFFFFFFFFu, l0, 2);
    l1 += __shfl_xor_sync(0xFFFFFFFFu, l1, 1);
    l1 += __shfl_xor_sync(0xFFFFFFFFu, l1, 2);
    float inv0 = 1.0f / l0, inv1 = 1.0f / l1;

    int b = bh >> 4, h = bh & 15;
    int srow = qt * 128 + wid * 16 + g;
    #pragma unroll
    for (int nt = 0; nt < 8; nt++) {
        int d = nt * 8 + t2;
        size_t o0 = (size_t)(b * SEQ + srow) * DIM + h * DH + d;
        size_t o1 = (size_t)(b * SEQ + srow + 8) * DIM + h * DH + d;
        *(float2*)&ao[o0] = make_float2(o[nt][0] * inv0, o[nt][1] * inv0);
        *(float2*)&ao[o1] = make_float2(o[nt][2] * inv1, o[nt][3] * inv1);
    }
}

// ===========================================================================
// Launch
// ===========================================================================
extern "C" void kernel_launch(void* const* d_in, const int* in_sizes, int n_in,
                              void* d_out, int out_size)
{
    (void)in_sizes; (void)n_in; (void)out_size;
    const float* x  = (const float*)d_in[0];
    const float* ns = (const float*)d_in[1];
    const float* Wq = (const float*)d_in[2];
    const float* Wk = (const float*)d_in[3];
    const float* Wv = (const float*)d_in[4];
    const float* Wo = (const float*)d_in[5];
    float* out = (float*)d_out;

    float *qkv, *ao, *sinT, *cosT;
    __nv_bfloat16 *ah, *al, *th, *tl, *qhp, *qlp, *khp, *klp, *vth, *vtl;
    cudaGetSymbolAddress((void**)&qkv, g_qkv);
    cudaGetSymbolAddress((void**)&ao, g_ao);
    cudaGetSymbolAddress((void**)&sinT, g_sinT);
    cudaGetSymbolAddress((void**)&cosT, g_cosT);
    cudaGetSymbolAddress((void**)&ah, g_ah);
    cudaGetSymbolAddress((void**)&al, g_al);
    cudaGetSymbolAddress((void**)&th, g_th);
    cudaGetSymbolAddress((void**)&tl, g_tl);
    cudaGetSymbolAddress((void**)&qhp, g_qh);
    cudaGetSymbolAddress((void**)&qlp, g_ql);
    cudaGetSymbolAddress((void**)&khp, g_kh);
    cudaGetSymbolAddress((void**)&klp, g_kl);
    cudaGetSymbolAddress((void**)&vth, g_vth);
    cudaGetSymbolAddress((void**)&vtl, g_vtl);

    cudaFuncSetAttribute(mma_gemm_kernel,
                         cudaFuncAttributeMaxDynamicSharedMemorySize, GEMM_SMEM);
    cudaFuncSetAttribute(flash_mma_kernel,
                         cudaFuncAttributeMaxDynamicSharedMemorySize, FL_SMEM);

    rope_table_kernel<<<(SEQ * 32) / 256, 256>>>(sinT, cosT);
    wsplit4_kernel<<<dim3(DIM / 32, DIM / 32, 4), 256>>>(Wq, Wk, Wv, Wo, th, tl);
    rmsnorm_split_kernel<<<ROWS, 256>>>(x, ns, ah, al);

    // Q, K, V projections in ONE launch (grid.x covers 3 weights)
    mma_gemm_kernel<<<dim3(3 * (DIM / 128), ROWS / 256), 256, GEMM_SMEM>>>(
        ah, al, th, tl, qkv);

    rope_split_kernel<<<(2 * ROWS * NH * 16) / 256, 256>>>(
        qkv, qkv + ROWS * DIM, sinT, cosT, qhp, qlp, khp, klp);
    vsplit_kernel<<<dim3(SEQ / 32, DH / 32, BATCH * NH), 256>>>(
        qkv + 2 * ROWS * DIM, vth, vtl);

    flash_mma_kernel<<<dim3(SEQ / 128, BATCH * NH), 256, FL_SMEM>>>(
        qhp, qlp, khp, klp, vth, vtl, ao);

    asplit_kernel<<<(ROWS * DIM) / (256 * 4), 256>>>(ao, ah, al);
    mma_gemm_kernel<<<dim3(DIM / 128, ROWS / 256), 256, GEMM_SMEM>>>(
        ah, al, th + (size_t)3 * DIM * DIM, tl + (size_t)3 * DIM * DIM, out);
}

// round 9
// speedup vs baseline: 1.1479x; 1.0046x over previous
#include <cuda_runtime.h>
#include <cuda_bf16.h>
#include <stdint.h>
#include <math.h>

#define BATCH 2
#define SEQ   2048
#define DIM   1024
#define ROWS  (BATCH*SEQ)   // 4096
#define NH    16
#define DH    64

// Scratch (allocation-free rule: __device__ globals)
__device__ float g_qkv[3*ROWS*DIM];          // Q,K,V fp32 outputs
__device__ float g_sinT[SEQ*32];             // RoPE tables [pos][i]
__device__ float g_cosT[SEQ*32];
__device__ __nv_bfloat16 g_ah[ROWS*DIM];     // x_norm split hi; later attn-out hi
__device__ __nv_bfloat16 g_al[ROWS*DIM];     // x_norm split lo; later attn-out lo
__device__ __nv_bfloat16 g_th[4*DIM*DIM];    // W^T split hi [4][N][K] (q,k,v,o)
__device__ __nv_bfloat16 g_tl[4*DIM*DIM];    // W^T split lo
// attention operands, head-contiguous layouts
__device__ __nv_bfloat16 g_qh[ROWS*DIM];     // Q hi (roped) [bh][s][d]
__device__ __nv_bfloat16 g_ql[ROWS*DIM];
__device__ __nv_bfloat16 g_kh[ROWS*DIM];     // K hi (roped) [bh][s][d]
__device__ __nv_bfloat16 g_kl[ROWS*DIM];
__device__ __nv_bfloat16 g_vth[ROWS*DIM];    // V^T hi [bh][d][s]
__device__ __nv_bfloat16 g_vtl[ROWS*DIM];

// ===========================================================================
// Portable (compute_103-safe) PTX helpers: mma.sync / ldmatrix / cp.async
// ===========================================================================
__device__ __forceinline__ uint32_t smem_u32(const void* p) {
    uint32_t a;
    asm("{ .reg .u64 t; cvta.to.shared.u64 t, %1; cvt.u32.u64 %0, t; }"
        : "=r"(a) : "l"(p));
    return a;
}
__device__ __forceinline__ void cp_async16(uint32_t saddr, const void* gaddr) {
    asm volatile("cp.async.cg.shared.global [%0], [%1], 16;"
                 :: "r"(saddr), "l"(gaddr));
}
__device__ __forceinline__ void cp_commit() {
    asm volatile("cp.async.commit_group;" ::: "memory");
}
__device__ __forceinline__ void ldsm4(uint32_t* r, uint32_t addr) {
    asm volatile("ldmatrix.sync.aligned.m8n8.x4.shared.b16 {%0,%1,%2,%3}, [%4];"
                 : "=r"(r[0]), "=r"(r[1]), "=r"(r[2]), "=r"(r[3]) : "r"(addr));
}
__device__ __forceinline__ void mma16816(float* c, const uint32_t* a,
                                         uint32_t b0, uint32_t b1) {
    asm volatile(
        "mma.sync.aligned.m16n8k16.row.col.f32.bf16.bf16.f32 "
        "{%0,%1,%2,%3}, {%4,%5,%6,%7}, {%8,%9}, {%0,%1,%2,%3};"
        : "+f"(c[0]), "+f"(c[1]), "+f"(c[2]), "+f"(c[3])
        : "r"(a[0]), "r"(a[1]), "r"(a[2]), "r"(a[3]), "r"(b0), "r"(b1));
}
__device__ __forceinline__ uint32_t pack2h(__nv_bfloat16 a, __nv_bfloat16 b) {
    __nv_bfloat162 t = __halves2bfloat162(a, b);
    return *reinterpret_cast<uint32_t*>(&t);
}
__device__ __forceinline__ uint32_t pack2f(float a, float b) {
    __nv_bfloat162 t = __floats2bfloat162_rn(a, b);
    return *reinterpret_cast<uint32_t*>(&t);
}
__device__ __forceinline__ void split2(float a, float b, uint32_t& hi, uint32_t& lo) {
    __nv_bfloat16 ha = __float2bfloat16(a), hb = __float2bfloat16(b);
    hi = pack2h(ha, hb);
    lo = pack2f(a - __bfloat162float(ha), b - __bfloat162float(hb));
}

// ===========================================================================
// RMSNorm fused with bf16 split: x -> (ah, al). x cached in registers.
// ===========================================================================
__global__ __launch_bounds__(256) void rmsnorm_split_kernel(
    const float* __restrict__ x, const float* __restrict__ sc,
    __nv_bfloat16* __restrict__ hi, __nv_bfloat16* __restrict__ lo)
{
    int row = blockIdx.x;
    const float* xr = x + (size_t)row * DIM;
    float v[4];
    float ss = 0.f;
    #pragma unroll
    for (int j = 0; j < 4; j++) {
        v[j] = xr[threadIdx.x + j * 256];
        ss = fmaf(v[j], v[j], ss);
    }
    __shared__ float red[256];
    red[threadIdx.x] = ss;
    __syncthreads();
    #pragma unroll
    for (int s = 128; s > 0; s >>= 1) {
        if (threadIdx.x < s) red[threadIdx.x] += red[threadIdx.x + s];
        __syncthreads();
    }
    float r = rsqrtf(red[0] * (1.0f / DIM) + 1e-6f);
    #pragma unroll
    for (int j = 0; j < 4; j++) {
        int i = threadIdx.x + j * 256;
        float y = v[j] * r * sc[i];
        __nv_bfloat16 h = __float2bfloat16(y);
        hi[(size_t)row * DIM + i] = h;
        lo[(size_t)row * DIM + i] = __float2bfloat16(y - __bfloat162float(h));
    }
}

// ===========================================================================
// Transpose + split for ALL FOUR weights + RoPE table, in one launch.
// z in [0,4): weight z transpose+split. z == 4: RoPE sin/cos table.
// ===========================================================================
__global__ __launch_bounds__(256) void wsplit4_kernel(
    const float* __restrict__ W0, const float* __restrict__ W1,
    const float* __restrict__ W2, const float* __restrict__ W3,
    __nv_bfloat16* __restrict__ Th, __nv_bfloat16* __restrict__ Tl,
    float* __restrict__ sinT, float* __restrict__ cosT)
{
    __shared__ float tile[32][33];
    int z = blockIdx.z;
    if (z == 4) {
        int idx = (blockIdx.y * 32 + blockIdx.x) * 256 + threadIdx.x;
        if (idx < SEQ * 32) {
            int pos = idx >> 5, i = idx & 31;
            float e = (2.0f * (float)i) / (float)DH;
            float theta = exp2f(-e * 19.931568569324174f);   // 1e6^-e
            float ang = (float)pos * theta;
            sinT[idx] = sinf(ang);
            cosT[idx] = cosf(ang);
        }
        return;
    }
    const float* W = (z == 0) ? W0 : (z == 1) ? W1 : (z == 2) ? W2 : W3;
    __nv_bfloat16* th = Th + (size_t)z * DIM * DIM;
    __nv_bfloat16* tl = Tl + (size_t)z * DIM * DIM;

    int k0 = blockIdx.y * 32, n0 = blockIdx.x * 32;
    int tx = threadIdx.x & 31, ty = threadIdx.x >> 5;   // 32 x 8
    #pragma unroll
    for (int i = 0; i < 32; i += 8)
        tile[ty + i][tx] = W[(size_t)(k0 + ty + i) * DIM + n0 + tx];
    __syncthreads();
    #pragma unroll
    for (int i = 0; i < 32; i += 8) {
        float v = tile[tx][ty + i];    // = W[k0+tx][n0+ty+i]
        __nv_bfloat16 h = __float2bfloat16(v);
        float r = v - __bfloat162float(h);
        size_t o = (size_t)(n0 + ty + i) * DIM + k0 + tx;
        th[o] = h;
        tl[o] = __float2bfloat16(r);
    }
}

// ===========================================================================
// bf16-split GEMM via mma.sync (validated rounds 5-8, unchanged).
// ===========================================================================
#define A_TILE_B 20480             // 256 rows x 80 bytes
#define B_TILE_B 10240             // 128 rows x 80 bytes
#define STG_B    (2*A_TILE_B + 2*B_TILE_B)   // 61440
#define GEMM_SMEM (2*STG_B)                   // 122880

__global__ __launch_bounds__(256) void mma_gemm_kernel(
    const __nv_bfloat16* __restrict__ Ah, const __nv_bfloat16* __restrict__ Al,
    const __nv_bfloat16* __restrict__ BhBase, const __nv_bfloat16* __restrict__ BlBase,
    float* __restrict__ CBase)
{
    extern __shared__ char smem[];
    uint32_t sb = smem_u32(smem);

    const int tid  = threadIdx.x;
    const int lane = tid & 31;
    const int wid  = tid >> 5;
    const int warp_m = wid & 3;
    const int warp_n = wid >> 2;
    const int which = blockIdx.x >> 3;               // weight index
    const int bm = blockIdx.y * 256;
    const int bn = (blockIdx.x & 7) * 128;

    const __nv_bfloat16* Bh = BhBase + (size_t)which * DIM * DIM;
    const __nv_bfloat16* Bl = BlBase + (size_t)which * DIM * DIM;
    float* C = CBase + (size_t)which * ROWS * DIM;

    float acc[4][8][4];
    #pragma unroll
    for (int i = 0; i < 4; i++)
        #pragma unroll
        for (int j = 0; j < 8; j++)
            #pragma unroll
            for (int q = 0; q < 4; q++) acc[i][j][q] = 0.f;

    auto load_stage = [&](int kt, int s) {
        const __nv_bfloat16* asrc[2] = {Ah, Al};
        #pragma unroll
        for (int t = 0; t < 2; t++) {
            #pragma unroll
            for (int i = 0; i < 4; i++) {
                int chunk = tid + i * 256;         // 0..1023
                int row = chunk >> 2, c = chunk & 3;
                cp_async16(sb + s * STG_B + t * A_TILE_B + row * 80 + c * 16,
                           asrc[t] + (size_t)(bm + row) * DIM + kt * 32 + c * 8);
            }
        }
        const __nv_bfloat16* bsrc[2] = {Bh, Bl};
        #pragma unroll
        for (int t = 0; t < 2; t++) {
            #pragma unroll
            for (int i = 0; i < 2; i++) {
                int chunk = tid + i * 256;         // 0..511
                int row = chunk >> 2, c = chunk & 3;
                cp_async16(sb + s * STG_B + 2 * A_TILE_B + t * B_TILE_B + row * 80 + c * 16,
                           bsrc[t] + (size_t)(bn + row) * DIM + kt * 32 + c * 8);
            }
        }
        cp_commit();
    };

    load_stage(0, 0);
    load_stage(1, 1);

    const int aRow = lane & 15;
    const int aK16 = (lane >> 4) * 16;
    const int bRow = (lane & 7) + ((lane >> 4) << 3);
    const int bK16 = ((lane >> 3) & 1) * 16;

    for (int kt = 0; kt < 32; kt++) {
        if (kt < 31) asm volatile("cp.async.wait_group 1;" ::: "memory");
        else         asm volatile("cp.async.wait_group 0;" ::: "memory");
        __syncthreads();

        uint32_t st  = sb + (kt & 1) * STG_B;
        uint32_t aHb = st + (warp_m * 64 + aRow) * 80 + aK16;
        uint32_t aLb = aHb + A_TILE_B;
        uint32_t bHb = st + 2 * A_TILE_B + (warp_n * 64 + bRow) * 80 + bK16;
        uint32_t bLb = bHb + B_TILE_B;

        #pragma unroll
        for (int ks = 0; ks < 2; ks++) {
            uint32_t koff = ks * 32;
            uint32_t fah[4][4], fal[4][4], fb[4][4];
            #pragma unroll
            for (int mt = 0; mt < 4; mt++) {
                ldsm4(fah[mt], aHb + mt * 1280 + koff);
                ldsm4(fal[mt], aLb + mt * 1280 + koff);
            }
            #pragma unroll
            for (int n2 = 0; n2 < 4; n2++)
                ldsm4(fb[n2], bHb + n2 * 1280 + koff);
            #pragma unroll
            for (int mt = 0; mt < 4; mt++)
                #pragma unroll
                for (int nt = 0; nt < 8; nt++)
                    mma16816(acc[mt][nt], fah[mt],
                             fb[nt >> 1][(nt & 1) * 2], fb[nt >> 1][(nt & 1) * 2 + 1]);
            #pragma unroll
            for (int mt = 0; mt < 4; mt++)
                #pragma unroll
                for (int nt = 0; nt < 8; nt++)
                    mma16816(acc[mt][nt], fal[mt],
                             fb[nt >> 1][(nt & 1) * 2], fb[nt >> 1][(nt & 1) * 2 + 1]);
            #pragma unroll
            for (int n2 = 0; n2 < 4; n2++)
                ldsm4(fb[n2], bLb + n2 * 1280 + koff);
            #pragma unroll
            for (int mt = 0; mt < 4; mt++)
                #pragma unroll
                for (int nt = 0; nt < 8; nt++)
                    mma16816(acc[mt][nt], fah[mt],
                             fb[nt >> 1][(nt & 1) * 2], fb[nt >> 1][(nt & 1) * 2 + 1]);
        }
        __syncthreads();
        if (kt + 2 < 32) load_stage(kt + 2, kt & 1);
    }

    const int g = lane >> 2, t2 = (lane & 3) * 2;
    #pragma unroll
    for (int mt = 0; mt < 4; mt++) {
        #pragma unroll
        for (int nt = 0; nt < 8; nt++) {
            int row = bm + warp_m * 64 + mt * 16 + g;
            int col = bn + warp_n * 64 + nt * 8 + t2;
            *(float2*)&C[(size_t)row * DIM + col] =
                make_float2(acc[mt][nt][0], acc[mt][nt][1]);
            *(float2*)&C[(size_t)(row + 8) * DIM + col] =
                make_float2(acc[mt][nt][2], acc[mt][nt][3]);
        }
    }
}

// ===========================================================================
// Merged RoPE-split (table-driven) + V transpose-split, one launch.
//   blocks [0, 8192): rope path on q,k
//   blocks [8192, 12288): vsplit path
// ===========================================================================
__global__ __launch_bounds__(256) void qkv_prep_kernel(
    const float* __restrict__ qkv,
    const float* __restrict__ sinT, const float* __restrict__ cosT,
    __nv_bfloat16* __restrict__ Qh, __nv_bfloat16* __restrict__ Ql,
    __nv_bfloat16* __restrict__ Kh, __nv_bfloat16* __restrict__ Kl,
    __nv_bfloat16* __restrict__ Vth, __nv_bfloat16* __restrict__ Vtl)
{
    __shared__ float tile[32][33];
    int bid = blockIdx.x;

    if (bid < 8192) {
        // ---- RoPE + split + relayout for q, k ----
        int idx = bid * 256 + threadIdx.x;   // 2^21 total
        int which = idx >> 20;
        int r   = idx & ((1 << 20) - 1);
        int row = r >> 8;
        int rem = r & 255;
        int head = rem >> 4;
        int i    = (rem & 15) * 2;

        const float* src = qkv + (size_t)which * ROWS * DIM
                               + (size_t)row * DIM + head * DH;
        int pos = row & (SEQ - 1);

        float2 sn = *(const float2*)&sinT[pos * 32 + i];
        float2 cs = *(const float2*)&cosT[pos * 32 + i];
        float2 x1 = *(const float2*)&src[i];
        float2 x2 = *(const float2*)&src[i + 32];

        float y1a = x1.x * cs.x - x2.x * sn.x, y2a = x1.x * sn.x + x2.x * cs.x;
        float y1b = x1.y * cs.y - x2.y * sn.y, y2b = x1.y * sn.y + x2.y * cs.y;

        int b = row >> 11, s = row & (SEQ - 1);
        size_t o = ((size_t)(b * NH + head) * SEQ + s) * DH + i;
        __nv_bfloat16* H = which ? Kh : Qh;
        __nv_bfloat16* L = which ? Kl : Ql;
        uint32_t hi, lo;
        split2(y1a, y1b, hi, lo);
        *(uint32_t*)&H[o] = hi;       *(uint32_t*)&L[o] = lo;
        split2(y2a, y2b, hi, lo);
        *(uint32_t*)&H[o + 32] = hi;  *(uint32_t*)&L[o + 32] = lo;
    } else {
        // ---- V transpose + split: [row][h*64+d] -> [bh][d][s] ----
        int b2 = bid - 8192;                 // [0, 4096)
        int s0 = (b2 & 63) * 32;             // 64 seq tiles
        int d0 = ((b2 >> 6) & 1) * 32;       // 2 dh tiles
        int bh = b2 >> 7;                    // 32 (b,h)
        int b = bh >> 4, h = bh & 15;
        const float* v = qkv + (size_t)2 * ROWS * DIM;
        int tx = threadIdx.x & 31, ty = threadIdx.x >> 5;
        #pragma unroll
        for (int i = 0; i < 32; i += 8)
            tile[ty + i][tx] = v[(size_t)(b * SEQ + s0 + ty + i) * DIM + h * DH + d0 + tx];
        __syncthreads();
        #pragma unroll
        for (int i = 0; i < 32; i += 8) {
            float val = tile[tx][ty + i];   // = v[s0+tx][d0+ty+i]
            __nv_bfloat16 hh = __float2bfloat16(val);
            size_t o = ((size_t)(bh * DH + d0 + ty + i)) * SEQ + s0 + tx;
            Vth[o] = hh;
            Vtl[o] = __float2bfloat16(val - __bfloat162float(hh));
        }
    }
}

// ===========================================================================
// Flash attention via mma.sync, split-bf16 (mainloop validated rounds 4-8).
// Epilogue now writes bf16 (hi, lo) split directly -> feeds O-projection.
// ===========================================================================
#define FP      144                 // smem row pitch (bytes)
#define FQ_OFF  0
#define FK_OFF  36864
#define FV_OFF  73728
#define FL_SMEM 110592

__global__ __launch_bounds__(256) void flash_mma_kernel(
    const __nv_bfloat16* __restrict__ Qh_, const __nv_bfloat16* __restrict__ Ql_,
    const __nv_bfloat16* __restrict__ Kh_, const __nv_bfloat16* __restrict__ Kl_,
    const __nv_bfloat16* __restrict__ Vth_, const __nv_bfloat16* __restrict__ Vtl_,
    __nv_bfloat16* __restrict__ Oh, __nv_bfloat16* __restrict__ Ol)
{
    extern __shared__ char smem[];
    uint32_t sb = smem_u32(smem);
    const int tid = threadIdx.x, lane = tid & 31, wid = tid >> 5;
    const int bh = blockIdx.y;
    const int qt = (gridDim.x - 1) - blockIdx.x;   // heavy tiles first
    const int nkt = 2 * (qt + 1);                  // 64-key chunks
    const size_t qkoff = (size_t)bh * SEQ * DH;
    const size_t voff  = (size_t)bh * DH * SEQ;

    // Q tile load (once)
    {
        const __nv_bfloat16* qs[2] = {Qh_ + qkoff, Ql_ + qkoff};
        #pragma unroll
        for (int i = 0; i < 8; i++) {
            int idx = tid + i * 256;           // 0..2047
            int t = idx >> 10, rem = idx & 1023;
            int row = rem >> 3, c = rem & 7;
            cp_async16(sb + FQ_OFF + t * 18432 + row * FP + c * 16,
                       qs[t] + (size_t)(qt * 128 + row) * DH + c * 8);
        }
        cp_commit();
    }

    auto load_kv = [&](int kt, int s) {
        int k0 = kt * 64;
        const __nv_bfloat16* ks_[2] = {Kh_ + qkoff, Kl_ + qkoff};
        const __nv_bfloat16* vs_[2] = {Vth_ + voff, Vtl_ + voff};
        #pragma unroll
        for (int i = 0; i < 4; i++) {
            int idx = tid + i * 256;           // 0..1023
            int t = idx >> 9, rem = idx & 511;
            int row = rem >> 3, c = rem & 7;
            cp_async16(sb + FK_OFF + s * 18432 + t * 9216 + row * FP + c * 16,
                       ks_[t] + (size_t)(k0 + row) * DH + c * 8);
        }
        #pragma unroll
        for (int i = 0; i < 4; i++) {
            int idx = tid + i * 256;
            int t = idx >> 9, rem = idx & 511;
            int row = rem >> 3, c = rem & 7;   // row = dh index, c = key chunk
            cp_async16(sb + FV_OFF + s * 18432 + t * 9216 + row * FP + c * 16,
                       vs_[t] + (size_t)row * SEQ + k0 + c * 8);
        }
        cp_commit();
    };
    load_kv(0, 0);
    load_kv(1, 1);

    const int g = lane >> 2, t2 = (lane & 3) * 2;
    const int aRow = lane & 15, aK16 = (lane >> 4) * 16;
    const int bRow = (lane & 7) + ((lane >> 4) << 3);
    const int bK16 = ((lane >> 3) & 1) * 16;

    asm volatile("cp.async.wait_group 2;" ::: "memory");
    __syncthreads();

    uint32_t qh[4][4], ql[4][4];
    {
        uint32_t base = sb + FQ_OFF + (wid * 16 + aRow) * FP + aK16;
        #pragma unroll
        for (int ks = 0; ks < 4; ks++) {
            ldsm4(qh[ks], base + ks * 32);
            ldsm4(ql[ks], base + 18432 + ks * 32);
        }
    }

    float o[8][4];
    #pragma unroll
    for (int nt = 0; nt < 8; nt++)
        #pragma unroll
        for (int j = 0; j < 4; j++) o[nt][j] = 0.f;
    float l0 = 0.f, l1 = 0.f;
    const int row0 = qt * 128 + wid * 16 + g;

    for (int kt = 0; kt < nkt; kt++) {
        if (kt < nkt - 1) asm volatile("cp.async.wait_group 1;" ::: "memory");
        else              asm volatile("cp.async.wait_group 0;" ::: "memory");
        __syncthreads();

        uint32_t stK = sb + FK_OFF + (kt & 1) * 18432;
        uint32_t stV = sb + FV_OFF + (kt & 1) * 18432;

        float S[8][4];
        #pragma unroll
        for (int nt = 0; nt < 8; nt++)
            #pragma unroll
            for (int j = 0; j < 4; j++) S[nt][j] = 0.f;

        #pragma unroll
        for (int ks = 0; ks < 4; ks++) {
            uint32_t fkh[4][4], fkl[4][4];
            #pragma unroll
            for (int n2 = 0; n2 < 4; n2++) {
                uint32_t a = stK + (n2 * 16 + bRow) * FP + bK16 + ks * 32;
                ldsm4(fkh[n2], a);
                ldsm4(fkl[n2], a + 9216);
            }
            #pragma unroll
            for (int nt = 0; nt < 8; nt++) {
                mma16816(S[nt], qh[ks], fkh[nt >> 1][(nt & 1) * 2], fkh[nt >> 1][(nt & 1) * 2 + 1]);
                mma16816(S[nt], qh[ks], fkl[nt >> 1][(nt & 1) * 2], fkl[nt >> 1][(nt & 1) * 2 + 1]);
                mma16816(S[nt], ql[ks], fkh[nt >> 1][(nt & 1) * 2], fkh[nt >> 1][(nt & 1) * 2 + 1]);
            }
        }

        uint32_t pah[4][4], pal[4][4];
        int k0 = kt * 64;
        #pragma unroll
        for (int nt = 0; nt < 8; nt++) {
            int col = k0 + nt * 8 + t2;
            float p0 = (col     <= row0)     ? __expf(S[nt][0] * 0.125f) : 0.f;
            float p1 = (col + 1 <= row0)     ? __expf(S[nt][1] * 0.125f) : 0.f;
            float p2 = (col     <= row0 + 8) ? __expf(S[nt][2] * 0.125f) : 0.f;
            float p3 = (col + 1 <= row0 + 8) ? __expf(S[nt][3] * 0.125f) : 0.f;
            l0 += p0 + p1;
            l1 += p2 + p3;
            __nv_bfloat16 h0 = __float2bfloat16(p0), h1 = __float2bfloat16(p1);
            __nv_bfloat16 h2 = __float2bfloat16(p2), h3 = __float2bfloat16(p3);
            float r0 = p0 - __bfloat162float(h0), r1 = p1 - __bfloat162float(h1);
            float r2 = p2 - __bfloat162float(h2), r3 = p3 - __bfloat162float(h3);
            int ks2 = nt >> 1, off = (nt & 1) * 2;
            pah[ks2][off]     = pack2h(h0, h1);
            pah[ks2][off + 1] = pack2h(h2, h3);
            pal[ks2][off]     = pack2f(r0, r1);
            pal[ks2][off + 1] = pack2f(r2, r3);
        }

        #pragma unroll
        for (int ks2 = 0; ks2 < 4; ks2++) {
            uint32_t fvh[4][4], fvl[4][4];
            #pragma unroll
            for (int n2 = 0; n2 < 4; n2++) {
                uint32_t a = stV + (n2 * 16 + bRow) * FP + bK16 + ks2 * 32;
                ldsm4(fvh[n2], a);
                ldsm4(fvl[n2], a + 9216);
            }
            #pragma unroll
            for (int nt = 0; nt < 8; nt++) {
                mma16816(o[nt], pah[ks2], fvh[nt >> 1][(nt & 1) * 2], fvh[nt >> 1][(nt & 1) * 2 + 1]);
                mma16816(o[nt], pah[ks2], fvl[nt >> 1][(nt & 1) * 2], fvl[nt >> 1][(nt & 1) * 2 + 1]);
                mma16816(o[nt], pal[ks2], fvh[nt >> 1][(nt & 1) * 2], fvh[nt >> 1][(nt & 1) * 2 + 1]);
            }
        }

        __syncthreads();
        if (kt + 2 < nkt) load_kv(kt + 2, kt & 1);
    }

    l0 += __shfl_xor_sync(0xFFFFFFFFu, l0, 1);
    l0 += __shfl_xor_sync(0xFFFFFFFFu, l0, 2);
    l1 += __shfl_xor_sync(0xFFFFFFFFu, l1, 1);
    l1 += __shfl_xor_sync(0xFFFFFFFFu, l1, 2);
    float inv0 = 1.0f / l0, inv1 = 1.0f / l1;

    int b = bh >> 4, h = bh & 15;
    int srow = qt * 128 + wid * 16 + g;
    #pragma unroll
    for (int nt = 0; nt < 8; nt++) {
        int d = nt * 8 + t2;
        size_t o0 = (size_t)(b * SEQ + srow) * DIM + h * DH + d;
        size_t o1 = (size_t)(b * SEQ + srow + 8) * DIM + h * DH + d;
        uint32_t hi, lo;
        split2(o[nt][0] * inv0, o[nt][1] * inv0, hi, lo);
        *(uint32_t*)&Oh[o0] = hi;  *(uint32_t*)&Ol[o0] = lo;
        split2(o[nt][2] * inv1, o[nt][3] * inv1, hi, lo);
        *(uint32_t*)&Oh[o1] = hi;  *(uint32_t*)&Ol[o1] = lo;
    }
}

// ===========================================================================
// Launch
// ===========================================================================
extern "C" void kernel_launch(void* const* d_in, const int* in_sizes, int n_in,
                              void* d_out, int out_size)
{
    (void)in_sizes; (void)n_in; (void)out_size;
    const float* x  = (const float*)d_in[0];
    const float* ns = (const float*)d_in[1];
    const float* Wq = (const float*)d_in[2];
    const float* Wk = (const float*)d_in[3];
    const float* Wv = (const float*)d_in[4];
    const float* Wo = (const float*)d_in[5];
    float* out = (float*)d_out;

    float *qkv, *sinT, *cosT;
    __nv_bfloat16 *ah, *al, *th, *tl, *qhp, *qlp, *khp, *klp, *vth, *vtl;
    cudaGetSymbolAddress((void**)&qkv, g_qkv);
    cudaGetSymbolAddress((void**)&sinT, g_sinT);
    cudaGetSymbolAddress((void**)&cosT, g_cosT);
    cudaGetSymbolAddress((void**)&ah, g_ah);
    cudaGetSymbolAddress((void**)&al, g_al);
    cudaGetSymbolAddress((void**)&th, g_th);
    cudaGetSymbolAddress((void**)&tl, g_tl);
    cudaGetSymbolAddress((void**)&qhp, g_qh);
    cudaGetSymbolAddress((void**)&qlp, g_ql);
    cudaGetSymbolAddress((void**)&khp, g_kh);
    cudaGetSymbolAddress((void**)&klp, g_kl);
    cudaGetSymbolAddress((void**)&vth, g_vth);
    cudaGetSymbolAddress((void**)&vtl, g_vtl);

    cudaFuncSetAttribute(mma_gemm_kernel,
                         cudaFuncAttributeMaxDynamicSharedMemorySize, GEMM_SMEM);
    cudaFuncSetAttribute(flash_mma_kernel,
                         cudaFuncAttributeMaxDynamicSharedMemorySize, FL_SMEM);

    // Weight transposes + RoPE table in one launch; RMSNorm+split fused.
    wsplit4_kernel<<<dim3(DIM / 32, DIM / 32, 5), 256>>>(
        Wq, Wk, Wv, Wo, th, tl, sinT, cosT);
    rmsnorm_split_kernel<<<ROWS, 256>>>(x, ns, ah, al);

    // Q, K, V projections in ONE launch (grid.x covers 3 weights)
    mma_gemm_kernel<<<dim3(3 * (DIM / 128), ROWS / 256), 256, GEMM_SMEM>>>(
        ah, al, th, tl, qkv);

    // RoPE split (q,k) + V transpose split, one launch
    qkv_prep_kernel<<<8192 + 4096, 256>>>(
        qkv, sinT, cosT, qhp, qlp, khp, klp, vth, vtl);

    // Flash attention; writes bf16 split (ah, al) directly
    flash_mma_kernel<<<dim3(SEQ / 128, BATCH * NH), 256, FL_SMEM>>>(
        qhp, qlp, khp, klp, vth, vtl, ah, al);

    // Output projection (weight index 3)
    mma_gemm_kernel<<<dim3(DIM / 128, ROWS / 256), 256, GEMM_SMEM>>>(
        ah, al, th + (size_t)3 * DIM * DIM, tl + (size_t)3 * DIM * DIM, out);
}

// round 10
// speedup vs baseline: 1.1718x; 1.0208x over previous
#include <cuda_runtime.h>
#include <cuda_bf16.h>
#include <stdint.h>
#include <math.h>

#define BATCH 2
#define SEQ   2048
#define DIM   1024
#define ROWS  (BATCH*SEQ)   // 4096
#define NH    16
#define DH    64

// Scratch (allocation-free rule: __device__ globals)
__device__ float g_qkv[3*ROWS*DIM];          // Q,K,V fp32 outputs
__device__ float g_sinT[SEQ*32];             // RoPE tables [pos][i]
__device__ float g_cosT[SEQ*32];
__device__ __nv_bfloat16 g_ah[ROWS*DIM];     // x_norm split hi; later attn-out hi
__device__ __nv_bfloat16 g_al[ROWS*DIM];     // x_norm split lo; later attn-out lo
__device__ __nv_bfloat16 g_th[4*DIM*DIM];    // W^T split hi [4][N][K] (q,k,v,o)
__device__ __nv_bfloat16 g_tl[4*DIM*DIM];    // W^T split lo
// attention operands, head-contiguous layouts
__device__ __nv_bfloat16 g_qh[ROWS*DIM];     // Q hi (roped) [bh][s][d]
__device__ __nv_bfloat16 g_ql[ROWS*DIM];
__device__ __nv_bfloat16 g_kh[ROWS*DIM];     // K hi (roped) [bh][s][d]
__device__ __nv_bfloat16 g_kl[ROWS*DIM];
__device__ __nv_bfloat16 g_vth[ROWS*DIM];    // V^T hi [bh][d][s]
__device__ __nv_bfloat16 g_vtl[ROWS*DIM];

// ===========================================================================
// Portable (compute_103-safe) PTX helpers: mma.sync / ldmatrix / cp.async
// ===========================================================================
__device__ __forceinline__ uint32_t smem_u32(const void* p) {
    uint32_t a;
    asm("{ .reg .u64 t; cvta.to.shared.u64 t, %1; cvt.u32.u64 %0, t; }"
        : "=r"(a) : "l"(p));
    return a;
}
__device__ __forceinline__ void cp_async16(uint32_t saddr, const void* gaddr) {
    asm volatile("cp.async.cg.shared.global [%0], [%1], 16;"
                 :: "r"(saddr), "l"(gaddr));
}
__device__ __forceinline__ void cp_commit() {
    asm volatile("cp.async.commit_group;" ::: "memory");
}
__device__ __forceinline__ void ldsm4(uint32_t* r, uint32_t addr) {
    asm volatile("ldmatrix.sync.aligned.m8n8.x4.shared.b16 {%0,%1,%2,%3}, [%4];"
                 : "=r"(r[0]), "=r"(r[1]), "=r"(r[2]), "=r"(r[3]) : "r"(addr));
}
__device__ __forceinline__ void mma16816(float* c, const uint32_t* a,
                                         uint32_t b0, uint32_t b1) {
    asm volatile(
        "mma.sync.aligned.m16n8k16.row.col.f32.bf16.bf16.f32 "
        "{%0,%1,%2,%3}, {%4,%5,%6,%7}, {%8,%9}, {%0,%1,%2,%3};"
        : "+f"(c[0]), "+f"(c[1]), "+f"(c[2]), "+f"(c[3])
        : "r"(a[0]), "r"(a[1]), "r"(a[2]), "r"(a[3]), "r"(b0), "r"(b1));
}
__device__ __forceinline__ uint32_t pack2h(__nv_bfloat16 a, __nv_bfloat16 b) {
    __nv_bfloat162 t = __halves2bfloat162(a, b);
    return *reinterpret_cast<uint32_t*>(&t);
}
__device__ __forceinline__ uint32_t pack2f(float a, float b) {
    __nv_bfloat162 t = __floats2bfloat162_rn(a, b);
    return *reinterpret_cast<uint32_t*>(&t);
}
__device__ __forceinline__ void split2(float a, float b, uint32_t& hi, uint32_t& lo) {
    __nv_bfloat16 ha = __float2bfloat16(a), hb = __float2bfloat16(b);
    hi = pack2h(ha, hb);
    lo = pack2f(a - __bfloat162float(ha), b - __bfloat162float(hb));
}

// ===========================================================================
// RMSNorm fused with bf16 split: x -> (ah, al). x cached in registers.
// ===========================================================================
__global__ __launch_bounds__(256) void rmsnorm_split_kernel(
    const float* __restrict__ x, const float* __restrict__ sc,
    __nv_bfloat16* __restrict__ hi, __nv_bfloat16* __restrict__ lo)
{
    int row = blockIdx.x;
    const float* xr = x + (size_t)row * DIM;
    float v[4];
    float ss = 0.f;
    #pragma unroll
    for (int j = 0; j < 4; j++) {
        v[j] = xr[threadIdx.x + j * 256];
        ss = fmaf(v[j], v[j], ss);
    }
    __shared__ float red[256];
    red[threadIdx.x] = ss;
    __syncthreads();
    #pragma unroll
    for (int s = 128; s > 0; s >>= 1) {
        if (threadIdx.x < s) red[threadIdx.x] += red[threadIdx.x + s];
        __syncthreads();
    }
    float r = rsqrtf(red[0] * (1.0f / DIM) + 1e-6f);
    #pragma unroll
    for (int j = 0; j < 4; j++) {
        int i = threadIdx.x + j * 256;
        float y = v[j] * r * sc[i];
        __nv_bfloat16 h = __float2bfloat16(y);
        hi[(size_t)row * DIM + i] = h;
        lo[(size_t)row * DIM + i] = __float2bfloat16(y - __bfloat162float(h));
    }
}

// ===========================================================================
// Transpose + split for ALL FOUR weights + RoPE table, in one launch.
// ===========================================================================
__global__ __launch_bounds__(256) void wsplit4_kernel(
    const float* __restrict__ W0, const float* __restrict__ W1,
    const float* __restrict__ W2, const float* __restrict__ W3,
    __nv_bfloat16* __restrict__ Th, __nv_bfloat16* __restrict__ Tl,
    float* __restrict__ sinT, float* __restrict__ cosT)
{
    __shared__ float tile[32][33];
    int z = blockIdx.z;
    if (z == 4) {
        int idx = (blockIdx.y * 32 + blockIdx.x) * 256 + threadIdx.x;
        if (idx < SEQ * 32) {
            int pos = idx >> 5, i = idx & 31;
            float e = (2.0f * (float)i) / (float)DH;
            float theta = exp2f(-e * 19.931568569324174f);   // 1e6^-e
            float ang = (float)pos * theta;
            sinT[idx] = sinf(ang);
            cosT[idx] = cosf(ang);
        }
        return;
    }
    const float* W = (z == 0) ? W0 : (z == 1) ? W1 : (z == 2) ? W2 : W3;
    __nv_bfloat16* th = Th + (size_t)z * DIM * DIM;
    __nv_bfloat16* tl = Tl + (size_t)z * DIM * DIM;

    int k0 = blockIdx.y * 32, n0 = blockIdx.x * 32;
    int tx = threadIdx.x & 31, ty = threadIdx.x >> 5;   // 32 x 8
    #pragma unroll
    for (int i = 0; i < 32; i += 8)
        tile[ty + i][tx] = W[(size_t)(k0 + ty + i) * DIM + n0 + tx];
    __syncthreads();
    #pragma unroll
    for (int i = 0; i < 32; i += 8) {
        float v = tile[tx][ty + i];    // = W[k0+tx][n0+ty+i]
        __nv_bfloat16 h = __float2bfloat16(v);
        float r = v - __bfloat162float(h);
        size_t o = (size_t)(n0 + ty + i) * DIM + k0 + tx;
        th[o] = h;
        tl[o] = __float2bfloat16(r);
    }
}

// ===========================================================================
// bf16-split GEMM via mma.sync. Block tile 256x128, BK=32, 8 warps (4x2),
// warp tile 64x64. NOW: 3-stage cp.async pipeline, ONE __syncthreads per
// K-tile, loads issued before the MMA block. MMA sequence unchanged.
// ===========================================================================
#define A_TILE_B 20480             // 256 rows x 80 bytes
#define B_TILE_B 10240             // 128 rows x 80 bytes
#define STG_B    (2*A_TILE_B + 2*B_TILE_B)   // 61440
#define GEMM_SMEM (3*STG_B)                   // 184320 (3 stages)

__global__ __launch_bounds__(256) void mma_gemm_kernel(
    const __nv_bfloat16* __restrict__ Ah, const __nv_bfloat16* __restrict__ Al,
    const __nv_bfloat16* __restrict__ BhBase, const __nv_bfloat16* __restrict__ BlBase,
    float* __restrict__ CBase)
{
    extern __shared__ char smem[];
    uint32_t sb = smem_u32(smem);

    const int tid  = threadIdx.x;
    const int lane = tid & 31;
    const int wid  = tid >> 5;
    const int warp_m = wid & 3;
    const int warp_n = wid >> 2;
    const int which = blockIdx.x >> 3;               // weight index
    const int bm = blockIdx.y * 256;
    const int bn = (blockIdx.x & 7) * 128;

    const __nv_bfloat16* Bh = BhBase + (size_t)which * DIM * DIM;
    const __nv_bfloat16* Bl = BlBase + (size_t)which * DIM * DIM;
    float* C = CBase + (size_t)which * ROWS * DIM;

    float acc[4][8][4];
    #pragma unroll
    for (int i = 0; i < 4; i++)
        #pragma unroll
        for (int j = 0; j < 8; j++)
            #pragma unroll
            for (int q = 0; q < 4; q++) acc[i][j][q] = 0.f;

    auto load_stage = [&](int kt, int s) {
        const __nv_bfloat16* asrc[2] = {Ah, Al};
        #pragma unroll
        for (int t = 0; t < 2; t++) {
            #pragma unroll
            for (int i = 0; i < 4; i++) {
                int chunk = tid + i * 256;         // 0..1023
                int row = chunk >> 2, c = chunk & 3;
                cp_async16(sb + s * STG_B + t * A_TILE_B + row * 80 + c * 16,
                           asrc[t] + (size_t)(bm + row) * DIM + kt * 32 + c * 8);
            }
        }
        const __nv_bfloat16* bsrc[2] = {Bh, Bl};
        #pragma unroll
        for (int t = 0; t < 2; t++) {
            #pragma unroll
            for (int i = 0; i < 2; i++) {
                int chunk = tid + i * 256;         // 0..511
                int row = chunk >> 2, c = chunk & 3;
                cp_async16(sb + s * STG_B + 2 * A_TILE_B + t * B_TILE_B + row * 80 + c * 16,
                           bsrc[t] + (size_t)(bn + row) * DIM + kt * 32 + c * 8);
            }
        }
        cp_commit();
    };

    load_stage(0, 0);
    load_stage(1, 1);

    const int aRow = lane & 15;
    const int aK16 = (lane >> 4) * 16;
    const int bRow = (lane & 7) + ((lane >> 4) << 3);
    const int bK16 = ((lane >> 3) & 1) * 16;

    int sNext = 2;   // stage index for kt+2
    for (int kt = 0; kt < 32; kt++) {
        if (kt < 31) asm volatile("cp.async.wait_group 1;" ::: "memory");
        else         asm volatile("cp.async.wait_group 0;" ::: "memory");
        __syncthreads();

        // issue next loads into the free third buffer, BEFORE the MMA block
        if (kt + 2 < 32) load_stage(kt + 2, sNext);

        int sCur = sNext + 1; if (sCur >= 3) sCur -= 3;   // == kt % 3
        uint32_t st  = sb + sCur * STG_B;
        uint32_t aHb = st + (warp_m * 64 + aRow) * 80 + aK16;
        uint32_t aLb = aHb + A_TILE_B;
        uint32_t bHb = st + 2 * A_TILE_B + (warp_n * 64 + bRow) * 80 + bK16;
        uint32_t bLb = bHb + B_TILE_B;
        sNext = sCur;   // next iteration's kt+2 lands where kt just lived

        #pragma unroll
        for (int ks = 0; ks < 2; ks++) {
            uint32_t koff = ks * 32;
            uint32_t fah[4][4], fal[4][4], fb[4][4];
            #pragma unroll
            for (int mt = 0; mt < 4; mt++) {
                ldsm4(fah[mt], aHb + mt * 1280 + koff);
                ldsm4(fal[mt], aLb + mt * 1280 + koff);
            }
            #pragma unroll
            for (int n2 = 0; n2 < 4; n2++)
                ldsm4(fb[n2], bHb + n2 * 1280 + koff);
            #pragma unroll
            for (int mt = 0; mt < 4; mt++)
                #pragma unroll
                for (int nt = 0; nt < 8; nt++)
                    mma16816(acc[mt][nt], fah[mt],
                             fb[nt >> 1][(nt & 1) * 2], fb[nt >> 1][(nt & 1) * 2 + 1]);
            #pragma unroll
            for (int mt = 0; mt < 4; mt++)
                #pragma unroll
                for (int nt = 0; nt < 8; nt++)
                    mma16816(acc[mt][nt], fal[mt],
                             fb[nt >> 1][(nt & 1) * 2], fb[nt >> 1][(nt & 1) * 2 + 1]);
            #pragma unroll
            for (int n2 = 0; n2 < 4; n2++)
                ldsm4(fb[n2], bLb + n2 * 1280 + koff);
            #pragma unroll
            for (int mt = 0; mt < 4; mt++)
                #pragma unroll
                for (int nt = 0; nt < 8; nt++)
                    mma16816(acc[mt][nt], fah[mt],
                             fb[nt >> 1][(nt & 1) * 2], fb[nt >> 1][(nt & 1) * 2 + 1]);
        }
    }

    const int g = lane >> 2, t2 = (lane & 3) * 2;
    #pragma unroll
    for (int mt = 0; mt < 4; mt++) {
        #pragma unroll
        for (int nt = 0; nt < 8; nt++) {
            int row = bm + warp_m * 64 + mt * 16 + g;
            int col = bn + warp_n * 64 + nt * 8 + t2;
            *(float2*)&C[(size_t)row * DIM + col] =
                make_float2(acc[mt][nt][0], acc[mt][nt][1]);
            *(float2*)&C[(size_t)(row + 8) * DIM + col] =
                make_float2(acc[mt][nt][2], acc[mt][nt][3]);
        }
    }
}

// ===========================================================================
// Merged RoPE-split (table-driven) + V transpose-split, one launch.
// ===========================================================================
__global__ __launch_bounds__(256) void qkv_prep_kernel(
    const float* __restrict__ qkv,
    const float* __restrict__ sinT, const float* __restrict__ cosT,
    __nv_bfloat16* __restrict__ Qh, __nv_bfloat16* __restrict__ Ql,
    __nv_bfloat16* __restrict__ Kh, __nv_bfloat16* __restrict__ Kl,
    __nv_bfloat16* __restrict__ Vth, __nv_bfloat16* __restrict__ Vtl)
{
    __shared__ float tile[32][33];
    int bid = blockIdx.x;

    if (bid < 8192) {
        int idx = bid * 256 + threadIdx.x;   // 2^21 total
        int which = idx >> 20;
        int r   = idx & ((1 << 20) - 1);
        int row = r >> 8;
        int rem = r & 255;
        int head = rem >> 4;
        int i    = (rem & 15) * 2;

        const float* src = qkv + (size_t)which * ROWS * DIM
                               + (size_t)row * DIM + head * DH;
        int pos = row & (SEQ - 1);

        float2 sn = *(const float2*)&sinT[pos * 32 + i];
        float2 cs = *(const float2*)&cosT[pos * 32 + i];
        float2 x1 = *(const float2*)&src[i];
        float2 x2 = *(const float2*)&src[i + 32];

        float y1a = x1.x * cs.x - x2.x * sn.x, y2a = x1.x * sn.x + x2.x * cs.x;
        float y1b = x1.y * cs.y - x2.y * sn.y, y2b = x1.y * sn.y + x2.y * cs.y;

        int b = row >> 11, s = row & (SEQ - 1);
        size_t o = ((size_t)(b * NH + head) * SEQ + s) * DH + i;
        __nv_bfloat16* H = which ? Kh : Qh;
        __nv_bfloat16* L = which ? Kl : Ql;
        uint32_t hi, lo;
        split2(y1a, y1b, hi, lo);
        *(uint32_t*)&H[o] = hi;       *(uint32_t*)&L[o] = lo;
        split2(y2a, y2b, hi, lo);
        *(uint32_t*)&H[o + 32] = hi;  *(uint32_t*)&L[o + 32] = lo;
    } else {
        int b2 = bid - 8192;                 // [0, 4096)
        int s0 = (b2 & 63) * 32;
        int d0 = ((b2 >> 6) & 1) * 32;
        int bh = b2 >> 7;
        int b = bh >> 4, h = bh & 15;
        const float* v = qkv + (size_t)2 * ROWS * DIM;
        int tx = threadIdx.x & 31, ty = threadIdx.x >> 5;
        #pragma unroll
        for (int i = 0; i < 32; i += 8)
            tile[ty + i][tx] = v[(size_t)(b * SEQ + s0 + ty + i) * DIM + h * DH + d0 + tx];
        __syncthreads();
        #pragma unroll
        for (int i = 0; i < 32; i += 8) {
            float val = tile[tx][ty + i];
            __nv_bfloat16 hh = __float2bfloat16(val);
            size_t o = ((size_t)(bh * DH + d0 + ty + i)) * SEQ + s0 + tx;
            Vth[o] = hh;
            Vtl[o] = __float2bfloat16(val - __bfloat162float(hh));
        }
    }
}

// ===========================================================================
// Flash attention via mma.sync, split-bf16. NOW: 3-stage KV pipeline, one
// __syncthreads per K-chunk. MMA sequence + epilogue unchanged.
// ===========================================================================
#define FP      144                 // smem row pitch (bytes)
#define FQ_OFF  0                   // Qh @0, Ql @18432 (128 rows x 144)
#define FK_OFF  36864               // + stage*18432; Kh +0, Kl +9216
#define FV_OFF  92160               // + stage*18432; Vh +0, Vl +9216
#define FL_SMEM 147456              // 36864 + 3*18432 (K) + 3*18432 (V)

__global__ __launch_bounds__(256) void flash_mma_kernel(
    const __nv_bfloat16* __restrict__ Qh_, const __nv_bfloat16* __restrict__ Ql_,
    const __nv_bfloat16* __restrict__ Kh_, const __nv_bfloat16* __restrict__ Kl_,
    const __nv_bfloat16* __restrict__ Vth_, const __nv_bfloat16* __restrict__ Vtl_,
    __nv_bfloat16* __restrict__ Oh, __nv_bfloat16* __restrict__ Ol)
{
    extern __shared__ char smem[];
    uint32_t sb = smem_u32(smem);
    const int tid = threadIdx.x, lane = tid & 31, wid = tid >> 5;
    const int bh = blockIdx.y;
    const int qt = (gridDim.x - 1) - blockIdx.x;   // heavy tiles first
    const int nkt = 2 * (qt + 1);                  // 64-key chunks
    const size_t qkoff = (size_t)bh * SEQ * DH;
    const size_t voff  = (size_t)bh * DH * SEQ;

    // Q tile load (once)
    {
        const __nv_bfloat16* qs[2] = {Qh_ + qkoff, Ql_ + qkoff};
        #pragma unroll
        for (int i = 0; i < 8; i++) {
            int idx = tid + i * 256;           // 0..2047
            int t = idx >> 10, rem = idx & 1023;
            int row = rem >> 3, c = rem & 7;
            cp_async16(sb + FQ_OFF + t * 18432 + row * FP + c * 16,
                       qs[t] + (size_t)(qt * 128 + row) * DH + c * 8);
        }
        cp_commit();
    }

    auto load_kv = [&](int kt, int s) {
        int k0 = kt * 64;
        const __nv_bfloat16* ks_[2] = {Kh_ + qkoff, Kl_ + qkoff};
        const __nv_bfloat16* vs_[2] = {Vth_ + voff, Vtl_ + voff};
        #pragma unroll
        for (int i = 0; i < 4; i++) {
            int idx = tid + i * 256;           // 0..1023
            int t = idx >> 9, rem = idx & 511;
            int row = rem >> 3, c = rem & 7;
            cp_async16(sb + FK_OFF + s * 18432 + t * 9216 + row * FP + c * 16,
                       ks_[t] + (size_t)(k0 + row) * DH + c * 8);
        }
        #pragma unroll
        for (int i = 0; i < 4; i++) {
            int idx = tid + i * 256;
            int t = idx >> 9, rem = idx & 511;
            int row = rem >> 3, c = rem & 7;   // row = dh index, c = key chunk
            cp_async16(sb + FV_OFF + s * 18432 + t * 9216 + row * FP + c * 16,
                       vs_[t] + (size_t)row * SEQ + k0 + c * 8);
        }
        cp_commit();
    };
    load_kv(0, 0);
    load_kv(1, 1);

    const int g = lane >> 2, t2 = (lane & 3) * 2;
    const int aRow = lane & 15, aK16 = (lane >> 4) * 16;
    const int bRow = (lane & 7) + ((lane >> 4) << 3);
    const int bK16 = ((lane >> 3) & 1) * 16;

    asm volatile("cp.async.wait_group 2;" ::: "memory");
    __syncthreads();

    uint32_t qh[4][4], ql[4][4];
    {
        uint32_t base = sb + FQ_OFF + (wid * 16 + aRow) * FP + aK16;
        #pragma unroll
        for (int ks = 0; ks < 4; ks++) {
            ldsm4(qh[ks], base + ks * 32);
            ldsm4(ql[ks], base + 18432 + ks * 32);
        }
    }

    float o[8][4];
    #pragma unroll
    for (int nt = 0; nt < 8; nt++)
        #pragma unroll
        for (int j = 0; j < 4; j++) o[nt][j] = 0.f;
    float l0 = 0.f, l1 = 0.f;
    const int row0 = qt * 128 + wid * 16 + g;

    int sNext = 2;
    for (int kt = 0; kt < nkt; kt++) {
        if (kt < nkt - 1) asm volatile("cp.async.wait_group 1;" ::: "memory");
        else              asm volatile("cp.async.wait_group 0;" ::: "memory");
        __syncthreads();

        if (kt + 2 < nkt) load_kv(kt + 2, sNext);

        int sCur = sNext + 1; if (sCur >= 3) sCur -= 3;   // == kt % 3
        uint32_t stK = sb + FK_OFF + sCur * 18432;
        uint32_t stV = sb + FV_OFF + sCur * 18432;
        sNext = sCur;

        float S[8][4];
        #pragma unroll
        for (int nt = 0; nt < 8; nt++)
            #pragma unroll
            for (int j = 0; j < 4; j++) S[nt][j] = 0.f;

        #pragma unroll
        for (int ks = 0; ks < 4; ks++) {
            uint32_t fkh[4][4], fkl[4][4];
            #pragma unroll
            for (int n2 = 0; n2 < 4; n2++) {
                uint32_t a = stK + (n2 * 16 + bRow) * FP + bK16 + ks * 32;
                ldsm4(fkh[n2], a);
                ldsm4(fkl[n2], a + 9216);
            }
            #pragma unroll
            for (int nt = 0; nt < 8; nt++) {
                mma16816(S[nt], qh[ks], fkh[nt >> 1][(nt & 1) * 2], fkh[nt >> 1][(nt & 1) * 2 + 1]);
                mma16816(S[nt], qh[ks], fkl[nt >> 1][(nt & 1) * 2], fkl[nt >> 1][(nt & 1) * 2 + 1]);
                mma16816(S[nt], ql[ks], fkh[nt >> 1][(nt & 1) * 2], fkh[nt >> 1][(nt & 1) * 2 + 1]);
            }
        }

        uint32_t pah[4][4], pal[4][4];
        int k0 = kt * 64;
        #pragma unroll
        for (int nt = 0; nt < 8; nt++) {
            int col = k0 + nt * 8 + t2;
            float p0 = (col     <= row0)     ? __expf(S[nt][0] * 0.125f) : 0.f;
            float p1 = (col + 1 <= row0)     ? __expf(S[nt][1] * 0.125f) : 0.f;
            float p2 = (col     <= row0 + 8) ? __expf(S[nt][2] * 0.125f) : 0.f;
            float p3 = (col + 1 <= row0 + 8) ? __expf(S[nt][3] * 0.125f) : 0.f;
            l0 += p0 + p1;
            l1 += p2 + p3;
            __nv_bfloat16 h0 = __float2bfloat16(p0), h1 = __float2bfloat16(p1);
            __nv_bfloat16 h2 = __float2bfloat16(p2), h3 = __float2bfloat16(p3);
            float r0 = p0 - __bfloat162float(h0), r1 = p1 - __bfloat162float(h1);
            float r2 = p2 - __bfloat162float(h2), r3 = p3 - __bfloat162float(h3);
            int ks2 = nt >> 1, off = (nt & 1) * 2;
            pah[ks2][off]     = pack2h(h0, h1);
            pah[ks2][off + 1] = pack2h(h2, h3);
            pal[ks2][off]     = pack2f(r0, r1);
            pal[ks2][off + 1] = pack2f(r2, r3);
        }

        #pragma unroll
        for (int ks2 = 0; ks2 < 4; ks2++) {
            uint32_t fvh[4][4], fvl[4][4];
            #pragma unroll
            for (int n2 = 0; n2 < 4; n2++) {
                uint32_t a = stV + (n2 * 16 + bRow) * FP + bK16 + ks2 * 32;
                ldsm4(fvh[n2], a);
                ldsm4(fvl[n2], a + 9216);
            }
            #pragma unroll
            for (int nt = 0; nt < 8; nt++) {
                mma16816(o[nt], pah[ks2], fvh[nt >> 1][(nt & 1) * 2], fvh[nt >> 1][(nt & 1) * 2 + 1]);
                mma16816(o[nt], pah[ks2], fvl[nt >> 1][(nt & 1) * 2], fvl[nt >> 1][(nt & 1) * 2 + 1]);
                mma16816(o[nt], pal[ks2], fvh[nt >> 1][(nt & 1) * 2], fvh[nt >> 1][(nt & 1) * 2 + 1]);
            }
        }
    }

    l0 += __shfl_xor_sync(0xFFFFFFFFu, l0, 1);
    l0 += __shfl_xor_sync(0xFFFFFFFFu, l0, 2);
    l1 += __shfl_xor_sync(0xFFFFFFFFu, l1, 1);
    l1 += __shfl_xor_sync(0xFFFFFFFFu, l1, 2);
    float inv0 = 1.0f / l0, inv1 = 1.0f / l1;

    int b = bh >> 4, h = bh & 15;
    int srow = qt * 128 + wid * 16 + g;
    #pragma unroll
    for (int nt = 0; nt < 8; nt++) {
        int d = nt * 8 + t2;
        size_t o0 = (size_t)(b * SEQ + srow) * DIM + h * DH + d;
        size_t o1 = (size_t)(b * SEQ + srow + 8) * DIM + h * DH + d;
        uint32_t hi, lo;
        split2(o[nt][0] * inv0, o[nt][1] * inv0, hi, lo);
        *(uint32_t*)&Oh[o0] = hi;  *(uint32_t*)&Ol[o0] = lo;
        split2(o[nt][2] * inv1, o[nt][3] * inv1, hi, lo);
        *(uint32_t*)&Oh[o1] = hi;  *(uint32_t*)&Ol[o1] = lo;
    }
}

// ===========================================================================
// Launch
// ===========================================================================
extern "C" void kernel_launch(void* const* d_in, const int* in_sizes, int n_in,
                              void* d_out, int out_size)
{
    (void)in_sizes; (void)n_in; (void)out_size;
    const float* x  = (const float*)d_in[0];
    const float* ns = (const float*)d_in[1];
    const float* Wq = (const float*)d_in[2];
    const float* Wk = (const float*)d_in[3];
    const float* Wv = (const float*)d_in[4];
    const float* Wo = (const float*)d_in[5];
    float* out = (float*)d_out;

    float *qkv, *sinT, *cosT;
    __nv_bfloat16 *ah, *al, *th, *tl, *qhp, *qlp, *khp, *klp, *vth, *vtl;
    cudaGetSymbolAddress((void**)&qkv, g_qkv);
    cudaGetSymbolAddress((void**)&sinT, g_sinT);
    cudaGetSymbolAddress((void**)&cosT, g_cosT);
    cudaGetSymbolAddress((void**)&ah, g_ah);
    cudaGetSymbolAddress((void**)&al, g_al);
    cudaGetSymbolAddress((void**)&th, g_th);
    cudaGetSymbolAddress((void**)&tl, g_tl);
    cudaGetSymbolAddress((void**)&qhp, g_qh);
    cudaGetSymbolAddress((void**)&qlp, g_ql);
    cudaGetSymbolAddress((void**)&khp, g_kh);
    cudaGetSymbolAddress((void**)&klp, g_kl);
    cudaGetSymbolAddress((void**)&vth, g_vth);
    cudaGetSymbolAddress((void**)&vtl, g_vtl);

    cudaFuncSetAttribute(mma_gemm_kernel,
                         cudaFuncAttributeMaxDynamicSharedMemorySize, GEMM_SMEM);
    cudaFuncSetAttribute(flash_mma_kernel,
                         cudaFuncAttributeMaxDynamicSharedMemorySize, FL_SMEM);

    wsplit4_kernel<<<dim3(DIM / 32, DIM / 32, 5), 256>>>(
        Wq, Wk, Wv, Wo, th, tl, sinT, cosT);
    rmsnorm_split_kernel<<<ROWS, 256>>>(x, ns, ah, al);

    mma_gemm_kernel<<<dim3(3 * (DIM / 128), ROWS / 256), 256, GEMM_SMEM>>>(
        ah, al, th, tl, qkv);

    qkv_prep_kernel<<<8192 + 4096, 256>>>(
        qkv, sinT, cosT, qhp, qlp, khp, klp, vth, vtl);

    flash_mma_kernel<<<dim3(SEQ / 128, BATCH * NH), 256, FL_SMEM>>>(
        qhp, qlp, khp, klp, vth, vtl, ah, al);

    mma_gemm_kernel<<<dim3(DIM / 128, ROWS / 256), 256, GEMM_SMEM>>>(
        ah, al, th + (size_t)3 * DIM * DIM, tl + (size_t)3 * DIM * DIM, out);
}

// round 11
// speedup vs baseline: 1.1766x; 1.0041x over previous
#include <cuda_runtime.h>
#include <cuda_bf16.h>
#include <stdint.h>
#include <math.h>

#define BATCH 2
#define SEQ   2048
#define DIM   1024
#define ROWS  (BATCH*SEQ)   // 4096
#define NH    16
#define DH    64

// Scratch (allocation-free rule: __device__ globals)
__device__ float g_qkv[3*ROWS*DIM];          // Q,K,V fp32 outputs
__device__ float g_sinT[SEQ*32];             // RoPE tables [pos][i]
__device__ float g_cosT[SEQ*32];
__device__ __nv_bfloat16 g_ah[ROWS*DIM];     // x_norm split hi; later attn-out hi
__device__ __nv_bfloat16 g_al[ROWS*DIM];     // x_norm split lo; later attn-out lo
__device__ __nv_bfloat16 g_th[4*DIM*DIM];    // W^T split hi [4][N][K] (q,k,v,o)
__device__ __nv_bfloat16 g_tl[4*DIM*DIM];    // W^T split lo
// attention operands, head-contiguous layouts
__device__ __nv_bfloat16 g_qh[ROWS*DIM];     // Q hi (roped) [bh][s][d]
__device__ __nv_bfloat16 g_ql[ROWS*DIM];
__device__ __nv_bfloat16 g_kh[ROWS*DIM];     // K hi (roped) [bh][s][d]
__device__ __nv_bfloat16 g_kl[ROWS*DIM];
__device__ __nv_bfloat16 g_vth[ROWS*DIM];    // V^T hi [bh][d][s]
__device__ __nv_bfloat16 g_vtl[ROWS*DIM];

// ===========================================================================
// Portable (compute_103-safe) PTX helpers: mma.sync / ldmatrix / cp.async
// ===========================================================================
__device__ __forceinline__ uint32_t smem_u32(const void* p) {
    uint32_t a;
    asm("{ .reg .u64 t; cvta.to.shared.u64 t, %1; cvt.u32.u64 %0, t; }"
        : "=r"(a) : "l"(p));
    return a;
}
__device__ __forceinline__ void cp_async16(uint32_t saddr, const void* gaddr) {
    asm volatile("cp.async.cg.shared.global [%0], [%1], 16;"
                 :: "r"(saddr), "l"(gaddr));
}
__device__ __forceinline__ void cp_commit() {
    asm volatile("cp.async.commit_group;" ::: "memory");
}
__device__ __forceinline__ void ldsm4(uint32_t* r, uint32_t addr) {
    asm volatile("ldmatrix.sync.aligned.m8n8.x4.shared.b16 {%0,%1,%2,%3}, [%4];"
                 : "=r"(r[0]), "=r"(r[1]), "=r"(r[2]), "=r"(r[3]) : "r"(addr));
}
__device__ __forceinline__ void mma16816(float* c, const uint32_t* a,
                                         uint32_t b0, uint32_t b1) {
    asm volatile(
        "mma.sync.aligned.m16n8k16.row.col.f32.bf16.bf16.f32 "
        "{%0,%1,%2,%3}, {%4,%5,%6,%7}, {%8,%9}, {%0,%1,%2,%3};"
        : "+f"(c[0]), "+f"(c[1]), "+f"(c[2]), "+f"(c[3])
        : "r"(a[0]), "r"(a[1]), "r"(a[2]), "r"(a[3]), "r"(b0), "r"(b1));
}
__device__ __forceinline__ uint32_t pack2h(__nv_bfloat16 a, __nv_bfloat16 b) {
    __nv_bfloat162 t = __halves2bfloat162(a, b);
    return *reinterpret_cast<uint32_t*>(&t);
}
__device__ __forceinline__ uint32_t pack2f(float a, float b) {
    __nv_bfloat162 t = __floats2bfloat162_rn(a, b);
    return *reinterpret_cast<uint32_t*>(&t);
}
__device__ __forceinline__ void split2(float a, float b, uint32_t& hi, uint32_t& lo) {
    __nv_bfloat16 ha = __float2bfloat16(a), hb = __float2bfloat16(b);
    hi = pack2h(ha, hb);
    lo = pack2f(a - __bfloat162float(ha), b - __bfloat162float(hb));
}

// ===========================================================================
// MERGED prologue: one launch does everything independent of the QKV GEMM.
//   z in [0,4): transpose+split weight z
//   z == 4   : RoPE sin/cos table
//   z in [5,9): RMSNorm + bf16 split, rows (z-5)*1024 + by*32 + bx
// ===========================================================================
__global__ __launch_bounds__(256) void prologue_kernel(
    const float* __restrict__ x, const float* __restrict__ sc,
    const float* __restrict__ W0, const float* __restrict__ W1,
    const float* __restrict__ W2, const float* __restrict__ W3,
    __nv_bfloat16* __restrict__ Th, __nv_bfloat16* __restrict__ Tl,
    float* __restrict__ sinT, float* __restrict__ cosT,
    __nv_bfloat16* __restrict__ ah, __nv_bfloat16* __restrict__ al)
{
    __shared__ float tile[32][33];
    __shared__ float red[256];
    int z = blockIdx.z;

    if (z == 4) {
        int idx = (blockIdx.y * 32 + blockIdx.x) * 256 + threadIdx.x;
        if (idx < SEQ * 32) {
            int pos = idx >> 5, i = idx & 31;
            float e = (2.0f * (float)i) / (float)DH;
            float theta = exp2f(-e * 19.931568569324174f);   // 1e6^-e
            float ang = (float)pos * theta;
            sinT[idx] = sinf(ang);
            cosT[idx] = cosf(ang);
        }
        return;
    }

    if (z >= 5) {
        // ---- RMSNorm + split for one row ----
        int row = (z - 5) * 1024 + blockIdx.y * 32 + blockIdx.x;
        const float* xr = x + (size_t)row * DIM;
        float v[4];
        float ss = 0.f;
        #pragma unroll
        for (int j = 0; j < 4; j++) {
            v[j] = xr[threadIdx.x + j * 256];
            ss = fmaf(v[j], v[j], ss);
        }
        red[threadIdx.x] = ss;
        __syncthreads();
        #pragma unroll
        for (int s = 128; s > 0; s >>= 1) {
            if (threadIdx.x < s) red[threadIdx.x] += red[threadIdx.x + s];
            __syncthreads();
        }
        float r = rsqrtf(red[0] * (1.0f / DIM) + 1e-6f);
        #pragma unroll
        for (int j = 0; j < 4; j++) {
            int i = threadIdx.x + j * 256;
            float y = v[j] * r * sc[i];
            __nv_bfloat16 h = __float2bfloat16(y);
            ah[(size_t)row * DIM + i] = h;
            al[(size_t)row * DIM + i] = __float2bfloat16(y - __bfloat162float(h));
        }
        return;
    }

    // ---- weight transpose + split ----
    const float* W = (z == 0) ? W0 : (z == 1) ? W1 : (z == 2) ? W2 : W3;
    __nv_bfloat16* th = Th + (size_t)z * DIM * DIM;
    __nv_bfloat16* tl = Tl + (size_t)z * DIM * DIM;

    int k0 = blockIdx.y * 32, n0 = blockIdx.x * 32;
    int tx = threadIdx.x & 31, ty = threadIdx.x >> 5;   // 32 x 8
    #pragma unroll
    for (int i = 0; i < 32; i += 8)
        tile[ty + i][tx] = W[(size_t)(k0 + ty + i) * DIM + n0 + tx];
    __syncthreads();
    #pragma unroll
    for (int i = 0; i < 32; i += 8) {
        float v = tile[tx][ty + i];    // = W[k0+tx][n0+ty+i]
        __nv_bfloat16 h = __float2bfloat16(v);
        float r = v - __bfloat162float(h);
        size_t o = (size_t)(n0 + ty + i) * DIM + k0 + tx;
        th[o] = h;
        tl[o] = __float2bfloat16(r);
    }
}

// ===========================================================================
// bf16-split GEMM via mma.sync. 3-stage cp.async pipeline (validated R10).
// ===========================================================================
#define A_TILE_B 20480             // 256 rows x 80 bytes
#define B_TILE_B 10240             // 128 rows x 80 bytes
#define STG_B    (2*A_TILE_B + 2*B_TILE_B)   // 61440
#define GEMM_SMEM (3*STG_B)                   // 184320 (3 stages)

__global__ __launch_bounds__(256) void mma_gemm_kernel(
    const __nv_bfloat16* __restrict__ Ah, const __nv_bfloat16* __restrict__ Al,
    const __nv_bfloat16* __restrict__ BhBase, const __nv_bfloat16* __restrict__ BlBase,
    float* __restrict__ CBase)
{
    extern __shared__ char smem[];
    uint32_t sb = smem_u32(smem);

    const int tid  = threadIdx.x;
    const int lane = tid & 31;
    const int wid  = tid >> 5;
    const int warp_m = wid & 3;
    const int warp_n = wid >> 2;
    const int which = blockIdx.x >> 3;               // weight index
    const int bm = blockIdx.y * 256;
    const int bn = (blockIdx.x & 7) * 128;

    const __nv_bfloat16* Bh = BhBase + (size_t)which * DIM * DIM;
    const __nv_bfloat16* Bl = BlBase + (size_t)which * DIM * DIM;
    float* C = CBase + (size_t)which * ROWS * DIM;

    float acc[4][8][4];
    #pragma unroll
    for (int i = 0; i < 4; i++)
        #pragma unroll
        for (int j = 0; j < 8; j++)
            #pragma unroll
            for (int q = 0; q < 4; q++) acc[i][j][q] = 0.f;

    auto load_stage = [&](int kt, int s) {
        const __nv_bfloat16* asrc[2] = {Ah, Al};
        #pragma unroll
        for (int t = 0; t < 2; t++) {
            #pragma unroll
            for (int i = 0; i < 4; i++) {
                int chunk = tid + i * 256;         // 0..1023
                int row = chunk >> 2, c = chunk & 3;
                cp_async16(sb + s * STG_B + t * A_TILE_B + row * 80 + c * 16,
                           asrc[t] + (size_t)(bm + row) * DIM + kt * 32 + c * 8);
            }
        }
        const __nv_bfloat16* bsrc[2] = {Bh, Bl};
        #pragma unroll
        for (int t = 0; t < 2; t++) {
            #pragma unroll
            for (int i = 0; i < 2; i++) {
                int chunk = tid + i * 256;         // 0..511
                int row = chunk >> 2, c = chunk & 3;
                cp_async16(sb + s * STG_B + 2 * A_TILE_B + t * B_TILE_B + row * 80 + c * 16,
                           bsrc[t] + (size_t)(bn + row) * DIM + kt * 32 + c * 8);
            }
        }
        cp_commit();
    };

    load_stage(0, 0);
    load_stage(1, 1);

    const int aRow = lane & 15;
    const int aK16 = (lane >> 4) * 16;
    const int bRow = (lane & 7) + ((lane >> 4) << 3);
    const int bK16 = ((lane >> 3) & 1) * 16;

    int sNext = 2;   // stage index for kt+2
    for (int kt = 0; kt < 32; kt++) {
        if (kt < 31) asm volatile("cp.async.wait_group 1;" ::: "memory");
        else         asm volatile("cp.async.wait_group 0;" ::: "memory");
        __syncthreads();

        if (kt + 2 < 32) load_stage(kt + 2, sNext);

        int sCur = sNext + 1; if (sCur >= 3) sCur -= 3;   // == kt % 3
        uint32_t st  = sb + sCur * STG_B;
        uint32_t aHb = st + (warp_m * 64 + aRow) * 80 + aK16;
        uint32_t aLb = aHb + A_TILE_B;
        uint32_t bHb = st + 2 * A_TILE_B + (warp_n * 64 + bRow) * 80 + bK16;
        uint32_t bLb = bHb + B_TILE_B;
        sNext = sCur;

        #pragma unroll
        for (int ks = 0; ks < 2; ks++) {
            uint32_t koff = ks * 32;
            uint32_t fah[4][4], fal[4][4], fb[4][4];
            #pragma unroll
            for (int mt = 0; mt < 4; mt++) {
                ldsm4(fah[mt], aHb + mt * 1280 + koff);
                ldsm4(fal[mt], aLb + mt * 1280 + koff);
            }
            #pragma unroll
            for (int n2 = 0; n2 < 4; n2++)
                ldsm4(fb[n2], bHb + n2 * 1280 + koff);
            #pragma unroll
            for (int mt = 0; mt < 4; mt++)
                #pragma unroll
                for (int nt = 0; nt < 8; nt++)
                    mma16816(acc[mt][nt], fah[mt],
                             fb[nt >> 1][(nt & 1) * 2], fb[nt >> 1][(nt & 1) * 2 + 1]);
            #pragma unroll
            for (int mt = 0; mt < 4; mt++)
                #pragma unroll
                for (int nt = 0; nt < 8; nt++)
                    mma16816(acc[mt][nt], fal[mt],
                             fb[nt >> 1][(nt & 1) * 2], fb[nt >> 1][(nt & 1) * 2 + 1]);
            #pragma unroll
            for (int n2 = 0; n2 < 4; n2++)
                ldsm4(fb[n2], bLb + n2 * 1280 + koff);
            #pragma unroll
            for (int mt = 0; mt < 4; mt++)
                #pragma unroll
                for (int nt = 0; nt < 8; nt++)
                    mma16816(acc[mt][nt], fah[mt],
                             fb[nt >> 1][(nt & 1) * 2], fb[nt >> 1][(nt & 1) * 2 + 1]);
        }
    }

    const int g = lane >> 2, t2 = (lane & 3) * 2;
    #pragma unroll
    for (int mt = 0; mt < 4; mt++) {
        #pragma unroll
        for (int nt = 0; nt < 8; nt++) {
            int row = bm + warp_m * 64 + mt * 16 + g;
            int col = bn + warp_n * 64 + nt * 8 + t2;
            *(float2*)&C[(size_t)row * DIM + col] =
                make_float2(acc[mt][nt][0], acc[mt][nt][1]);
            *(float2*)&C[(size_t)(row + 8) * DIM + col] =
                make_float2(acc[mt][nt][2], acc[mt][nt][3]);
        }
    }
}

// ===========================================================================
// Merged RoPE-split (float4 vectorized) + V transpose-split (4B stores).
//   blocks [0, 4096): rope path on q,k  (thread = 4 freqs of one row/head)
//   blocks [4096, 8192): vsplit path
// ===========================================================================
__global__ __launch_bounds__(256) void qkv_prep_kernel(
    const float* __restrict__ qkv,
    const float* __restrict__ sinT, const float* __restrict__ cosT,
    __nv_bfloat16* __restrict__ Qh, __nv_bfloat16* __restrict__ Ql,
    __nv_bfloat16* __restrict__ Kh, __nv_bfloat16* __restrict__ Kl,
    __nv_bfloat16* __restrict__ Vth, __nv_bfloat16* __restrict__ Vtl)
{
    __shared__ float tile[32][33];
    int bid = blockIdx.x;

    if (bid < 4096) {
        // ---- RoPE + split + relayout for q, k (float4 per thread) ----
        int idx = bid * 256 + threadIdx.x;     // 2^20 total
        int which = idx >> 19;                 // 0=q, 1=k
        int r   = idx & ((1 << 19) - 1);
        int row = r >> 7;                      // 128 = 16 heads * 8
        int rem = r & 127;
        int head = rem >> 3;
        int i4   = (rem & 7) * 4;

        const float* src = qkv + (size_t)which * ROWS * DIM
                               + (size_t)row * DIM + head * DH;
        int pos = row & (SEQ - 1);

        float4 sn = *(const float4*)&sinT[pos * 32 + i4];
        float4 cs = *(const float4*)&cosT[pos * 32 + i4];
        float4 x1 = *(const float4*)&src[i4];
        float4 x2 = *(const float4*)&src[i4 + 32];

        float y1a = x1.x * cs.x - x2.x * sn.x, y2a = x1.x * sn.x + x2.x * cs.x;
        float y1b = x1.y * cs.y - x2.y * sn.y, y2b = x1.y * sn.y + x2.y * cs.y;
        float y1c = x1.z * cs.z - x2.z * sn.z, y2c = x1.z * sn.z + x2.z * cs.z;
        float y1d = x1.w * cs.w - x2.w * sn.w, y2d = x1.w * sn.w + x2.w * cs.w;

        int b = row >> 11, s = row & (SEQ - 1);
        size_t o = ((size_t)(b * NH + head) * SEQ + s) * DH + i4;
        __nv_bfloat16* H = which ? Kh : Qh;
        __nv_bfloat16* L = which ? Kl : Ql;
        uint32_t h0, l0, h1, l1;
        split2(y1a, y1b, h0, l0);
        split2(y1c, y1d, h1, l1);
        *(uint2*)&H[o] = make_uint2(h0, h1);
        *(uint2*)&L[o] = make_uint2(l0, l1);
        split2(y2a, y2b, h0, l0);
        split2(y2c, y2d, h1, l1);
        *(uint2*)&H[o + 32] = make_uint2(h0, h1);
        *(uint2*)&L[o + 32] = make_uint2(l0, l1);
    } else {
        // ---- V transpose + split: [row][h*64+d] -> [bh][d][s], 4B stores ----
        int b2 = bid - 4096;                 // [0, 4096)
        int s0 = (b2 & 63) * 32;             // 64 seq tiles
        int d0 = ((b2 >> 6) & 1) * 32;       // 2 dh tiles
        int bh = b2 >> 7;                    // 32 (b,h)
        int b = bh >> 4, h = bh & 15;
        const float* v = qkv + (size_t)2 * ROWS * DIM;
        int tx = threadIdx.x & 31, ty = threadIdx.x >> 5;
        #pragma unroll
        for (int i = 0; i < 32; i += 8)
            tile[ty + i][tx] = v[(size_t)(b * SEQ + s0 + ty + i) * DIM + h * DH + d0 + tx];
        __syncthreads();
        // store: thread covers (d = dy, dy+16) x (s pair = 2*sx, 2*sx+1)
        int sx = threadIdx.x & 15;           // seq-pair index
        int dy = threadIdx.x >> 4;           // 0..15
        #pragma unroll
        for (int dd = 0; dd < 32; dd += 16) {
            int d = dy + dd;
            float va = tile[sx * 2][d];
            float vb = tile[sx * 2 + 1][d];
            uint32_t hi, lo;
            split2(va, vb, hi, lo);
            size_t o = ((size_t)(bh * DH + d0 + d)) * SEQ + s0 + sx * 2;
            *(uint32_t*)&Vth[o] = hi;
            *(uint32_t*)&Vtl[o] = lo;
        }
    }
}

// ===========================================================================
// Flash attention via mma.sync, split-bf16, 3-stage KV pipeline (R10).
// ===========================================================================
#define FP      144                 // smem row pitch (bytes)
#define FQ_OFF  0
#define FK_OFF  36864
#define FV_OFF  92160
#define FL_SMEM 147456

__global__ __launch_bounds__(256) void flash_mma_kernel(
    const __nv_bfloat16* __restrict__ Qh_, const __nv_bfloat16* __restrict__ Ql_,
    const __nv_bfloat16* __restrict__ Kh_, const __nv_bfloat16* __restrict__ Kl_,
    const __nv_bfloat16* __restrict__ Vth_, const __nv_bfloat16* __restrict__ Vtl_,
    __nv_bfloat16* __restrict__ Oh, __nv_bfloat16* __restrict__ Ol)
{
    extern __shared__ char smem[];
    uint32_t sb = smem_u32(smem);
    const int tid = threadIdx.x, lane = tid & 31, wid = tid >> 5;
    const int bh = blockIdx.y;
    const int qt = (gridDim.x - 1) - blockIdx.x;   // heavy tiles first
    const int nkt = 2 * (qt + 1);                  // 64-key chunks
    const size_t qkoff = (size_t)bh * SEQ * DH;
    const size_t voff  = (size_t)bh * DH * SEQ;

    // Q tile load (once)
    {
        const __nv_bfloat16* qs[2] = {Qh_ + qkoff, Ql_ + qkoff};
        #pragma unroll
        for (int i = 0; i < 8; i++) {
            int idx = tid + i * 256;           // 0..2047
            int t = idx >> 10, rem = idx & 1023;
            int row = rem >> 3, c = rem & 7;
            cp_async16(sb + FQ_OFF + t * 18432 + row * FP + c * 16,
                       qs[t] + (size_t)(qt * 128 + row) * DH + c * 8);
        }
        cp_commit();
    }

    auto load_kv = [&](int kt, int s) {
        int k0 = kt * 64;
        const __nv_bfloat16* ks_[2] = {Kh_ + qkoff, Kl_ + qkoff};
        const __nv_bfloat16* vs_[2] = {Vth_ + voff, Vtl_ + voff};
        #pragma unroll
        for (int i = 0; i < 4; i++) {
            int idx = tid + i * 256;           // 0..1023
            int t = idx >> 9, rem = idx & 511;
            int row = rem >> 3, c = rem & 7;
            cp_async16(sb + FK_OFF + s * 18432 + t * 9216 + row * FP + c * 16,
                       ks_[t] + (size_t)(k0 + row) * DH + c * 8);
        }
        #pragma unroll
        for (int i = 0; i < 4; i++) {
            int idx = tid + i * 256;
            int t = idx >> 9, rem = idx & 511;
            int row = rem >> 3, c = rem & 7;   // row = dh index, c = key chunk
            cp_async16(sb + FV_OFF + s * 18432 + t * 9216 + row * FP + c * 16,
                       vs_[t] + (size_t)row * SEQ + k0 + c * 8);
        }
        cp_commit();
    };
    load_kv(0, 0);
    load_kv(1, 1);

    const int g = lane >> 2, t2 = (lane & 3) * 2;
    const int aRow = lane & 15, aK16 = (lane >> 4) * 16;
    const int bRow = (lane & 7) + ((lane >> 4) << 3);
    const int bK16 = ((lane >> 3) & 1) * 16;

    asm volatile("cp.async.wait_group 2;" ::: "memory");
    __syncthreads();

    uint32_t qh[4][4], ql[4][4];
    {
        uint32_t base = sb + FQ_OFF + (wid * 16 + aRow) * FP + aK16;
        #pragma unroll
        for (int ks = 0; ks < 4; ks++) {
            ldsm4(qh[ks], base + ks * 32);
            ldsm4(ql[ks], base + 18432 + ks * 32);
        }
    }

    float o[8][4];
    #pragma unroll
    for (int nt = 0; nt < 8; nt++)
        #pragma unroll
        for (int j = 0; j < 4; j++) o[nt][j] = 0.f;
    float l0 = 0.f, l1 = 0.f;
    const int row0 = qt * 128 + wid * 16 + g;

    int sNext = 2;
    for (int kt = 0; kt < nkt; kt++) {
        if (kt < nkt - 1) asm volatile("cp.async.wait_group 1;" ::: "memory");
        else              asm volatile("cp.async.wait_group 0;" ::: "memory");
        __syncthreads();

        if (kt + 2 < nkt) load_kv(kt + 2, sNext);

        int sCur = sNext + 1; if (sCur >= 3) sCur -= 3;   // == kt % 3
        uint32_t stK = sb + FK_OFF + sCur * 18432;
        uint32_t stV = sb + FV_OFF + sCur * 18432;
        sNext = sCur;

        float S[8][4];
        #pragma unroll
        for (int nt = 0; nt < 8; nt++)
            #pragma unroll
            for (int j = 0; j < 4; j++) S[nt][j] = 0.f;

        #pragma unroll
        for (int ks = 0; ks < 4; ks++) {
            uint32_t fkh[4][4], fkl[4][4];
            #pragma unroll
            for (int n2 = 0; n2 < 4; n2++) {
                uint32_t a = stK + (n2 * 16 + bRow) * FP + bK16 + ks * 32;
                ldsm4(fkh[n2], a);
                ldsm4(fkl[n2], a + 9216);
            }
            #pragma unroll
            for (int nt = 0; nt < 8; nt++) {
                mma16816(S[nt], qh[ks], fkh[nt >> 1][(nt & 1) * 2], fkh[nt >> 1][(nt & 1) * 2 + 1]);
                mma16816(S[nt], qh[ks], fkl[nt >> 1][(nt & 1) * 2], fkl[nt >> 1][(nt & 1) * 2 + 1]);
                mma16816(S[nt], ql[ks], fkh[nt >> 1][(nt & 1) * 2], fkh[nt >> 1][(nt & 1) * 2 + 1]);
            }
        }

        uint32_t pah[4][4], pal[4][4];
        int k0 = kt * 64;
        #pragma unroll
        for (int nt = 0; nt < 8; nt++) {
            int col = k0 + nt * 8 + t2;
            float p0 = (col     <= row0)     ? __expf(S[nt][0] * 0.125f) : 0.f;
            float p1 = (col + 1 <= row0)     ? __expf(S[nt][1] * 0.125f) : 0.f;
            float p2 = (col     <= row0 + 8) ? __expf(S[nt][2] * 0.125f) : 0.f;
            float p3 = (col + 1 <= row0 + 8) ? __expf(S[nt][3] * 0.125f) : 0.f;
            l0 += p0 + p1;
            l1 += p2 + p3;
            __nv_bfloat16 h0 = __float2bfloat16(p0), h1 = __float2bfloat16(p1);
            __nv_bfloat16 h2 = __float2bfloat16(p2), h3 = __float2bfloat16(p3);
            float r0 = p0 - __bfloat162float(h0), r1 = p1 - __bfloat162float(h1);
            float r2 = p2 - __bfloat162float(h2), r3 = p3 - __bfloat162float(h3);
            int ks2 = nt >> 1, off = (nt & 1) * 2;
            pah[ks2][off]     = pack2h(h0, h1);
            pah[ks2][off + 1] = pack2h(h2, h3);
            pal[ks2][off]     = pack2f(r0, r1);
            pal[ks2][off + 1] = pack2f(r2, r3);
        }

        #pragma unroll
        for (int ks2 = 0; ks2 < 4; ks2++) {
            uint32_t fvh[4][4], fvl[4][4];
            #pragma unroll
            for (int n2 = 0; n2 < 4; n2++) {
                uint32_t a = stV + (n2 * 16 + bRow) * FP + bK16 + ks2 * 32;
                ldsm4(fvh[n2], a);
                ldsm4(fvl[n2], a + 9216);
            }
            #pragma unroll
            for (int nt = 0; nt < 8; nt++) {
                mma16816(o[nt], pah[ks2], fvh[nt >> 1][(nt & 1) * 2], fvh[nt >> 1][(nt & 1) * 2 + 1]);
                mma16816(o[nt], pah[ks2], fvl[nt >> 1][(nt & 1) * 2], fvl[nt >> 1][(nt & 1) * 2 + 1]);
                mma16816(o[nt], pal[ks2], fvh[nt >> 1][(nt & 1) * 2], fvh[nt >> 1][(nt & 1) * 2 + 1]);
            }
        }
    }

    l0 += __shfl_xor_sync(0xFFFFFFFFu, l0, 1);
    l0 += __shfl_xor_sync(0xFFFFFFFFu, l0, 2);
    l1 += __shfl_xor_sync(0xFFFFFFFFu, l1, 1);
    l1 += __shfl_xor_sync(0xFFFFFFFFu, l1, 2);
    float inv0 = 1.0f / l0, inv1 = 1.0f / l1;

    int b = bh >> 4, h = bh & 15;
    int srow = qt * 128 + wid * 16 + g;
    #pragma unroll
    for (int nt = 0; nt < 8; nt++) {
        int d = nt * 8 + t2;
        size_t o0 = (size_t)(b * SEQ + srow) * DIM + h * DH + d;
        size_t o1 = (size_t)(b * SEQ + srow + 8) * DIM + h * DH + d;
        uint32_t hi, lo;
        split2(o[nt][0] * inv0, o[nt][1] * inv0, hi, lo);
        *(uint32_t*)&Oh[o0] = hi;  *(uint32_t*)&Ol[o0] = lo;
        split2(o[nt][2] * inv1, o[nt][3] * inv1, hi, lo);
        *(uint32_t*)&Oh[o1] = hi;  *(uint32_t*)&Ol[o1] = lo;
    }
}

// ===========================================================================
// Launch
// ===========================================================================
extern "C" void kernel_launch(void* const* d_in, const int* in_sizes, int n_in,
                              void* d_out, int out_size)
{
    (void)in_sizes; (void)n_in; (void)out_size;
    const float* x  = (const float*)d_in[0];
    const float* ns = (const float*)d_in[1];
    const float* Wq = (const float*)d_in[2];
    const float* Wk = (const float*)d_in[3];
    const float* Wv = (const float*)d_in[4];
    const float* Wo = (const float*)d_in[5];
    float* out = (float*)d_out;

    float *qkv, *sinT, *cosT;
    __nv_bfloat16 *ah, *al, *th, *tl, *qhp, *qlp, *khp, *klp, *vth, *vtl;
    cudaGetSymbolAddress((void**)&qkv, g_qkv);
    cudaGetSymbolAddress((void**)&sinT, g_sinT);
    cudaGetSymbolAddress((void**)&cosT, g_cosT);
    cudaGetSymbolAddress((void**)&ah, g_ah);
    cudaGetSymbolAddress((void**)&al, g_al);
    cudaGetSymbolAddress((void**)&th, g_th);
    cudaGetSymbolAddress((void**)&tl, g_tl);
    cudaGetSymbolAddress((void**)&qhp, g_qh);
    cudaGetSymbolAddress((void**)&qlp, g_ql);
    cudaGetSymbolAddress((void**)&khp, g_kh);
    cudaGetSymbolAddress((void**)&klp, g_kl);
    cudaGetSymbolAddress((void**)&vth, g_vth);
    cudaGetSymbolAddress((void**)&vtl, g_vtl);

    cudaFuncSetAttribute(mma_gemm_kernel,
                         cudaFuncAttributeMaxDynamicSharedMemorySize, GEMM_SMEM);
    cudaFuncSetAttribute(flash_mma_kernel,
                         cudaFuncAttributeMaxDynamicSharedMemorySize, FL_SMEM);

    // Everything independent of the QKV GEMM in ONE launch:
    // weights transpose+split, RoPE table, RMSNorm+split.
    prologue_kernel<<<dim3(DIM / 32, DIM / 32, 9), 256>>>(
        x, ns, Wq, Wk, Wv, Wo, th, tl, sinT, cosT, ah, al);

    // Q, K, V projections in ONE launch (grid.x covers 3 weights)
    mma_gemm_kernel<<<dim3(3 * (DIM / 128), ROWS / 256), 256, GEMM_SMEM>>>(
        ah, al, th, tl, qkv);

    // RoPE split (q,k) + V transpose split, one launch, vectorized
    qkv_prep_kernel<<<4096 + 4096, 256>>>(
        qkv, sinT, cosT, qhp, qlp, khp, klp, vth, vtl);

    // Flash attention; writes bf16 split (ah, al) directly
    flash_mma_kernel<<<dim3(SEQ / 128, BATCH * NH), 256, FL_SMEM>>>(
        qhp, qlp, khp, klp, vth, vtl, ah, al);

    // Output projection (weight index 3)
    mma_gemm_kernel<<<dim3(DIM / 128, ROWS / 256), 256, GEMM_SMEM>>>(
        ah, al, th + (size_t)3 * DIM * DIM, tl + (size_t)3 * DIM * DIM, out);
}